// round 14
// baseline (speedup 1.0000x reference)
#include <cuda_runtime.h>
#include <cuda_fp16.h>
#include <math.h>
#include <stdint.h>

#define BB   32
#define SS   197
#define NTOK 196
#define DD   768
#define NHH  12
#define HDD  64
#define FF   3072
#define LLAY 12
#define NLAB 1000
#define MROWS (BB*SS)
#define MPAT  (BB*NTOK)
#define BHN   (BB*NHH)

// ===== Scratch =====
__device__ __half g_ph[MPAT * DD], g_pl[MPAT * DD];
__device__ __half g_hh[MROWS * DD], g_hl[MROWS * DD];
__device__ __half g_oh[MROWS * DD], g_ol[MROWS * DD];
__device__ __half g_mh[MROWS * FF], g_ml[MROWS * FF];
__device__ __half g_qkvh[MROWS * 3 * DD], g_qkvl[MROWS * 3 * DD];
__device__ __half g_wqkv[LLAY*3*DD*DD];
__device__ __half g_wo[LLAY*DD*DD];
__device__ __half g_w1[LLAY*FF*DD];
__device__ __half g_w2[LLAY*DD*FF];
__device__ __half g_pw[DD * DD];
__device__ float g_x[MROWS * DD];
__device__ float g_cls[BB * DD];

// ===== helpers =====
__device__ __forceinline__ uint32_t s2u(const void* p) {
    uint32_t a;
    asm("{ .reg .u64 t; cvta.to.shared.u64 t, %1; cvt.u32.u64 %0, t; }" : "=r"(a) : "l"(p));
    return a;
}
__device__ __forceinline__ void split_f16(float v, __half& h, __half& l) {
    h = __float2half_rn(v);
    l = __float2half_rn(v - __half2float(h));
}
__device__ __forceinline__ uint32_t pack_f16(float v0, float v1) {
    return ((uint32_t)__half_as_ushort(__float2half_rn(v1)) << 16)
         | __half_as_ushort(__float2half_rn(v0));
}
__device__ __forceinline__ uint32_t split_pack(float v0, float v1, uint32_t& lo) {
    __half h0, l0, h1, l1;
    split_f16(v0, h0, l0); split_f16(v1, h1, l1);
    lo = ((uint32_t)__half_as_ushort(l1) << 16) | __half_as_ushort(l0);
    return ((uint32_t)__half_as_ushort(h1) << 16) | __half_as_ushort(h0);
}
__device__ __forceinline__ void cpa16(uint32_t s, const void* g) {
    asm volatile("cp.async.cg.shared.global [%0], [%1], 16;"
        :: "r"(s), "l"(g) : "memory");
}
#define CP_COMMIT() asm volatile("cp.async.commit_group;" ::: "memory")
#define CP_WAIT2()  asm volatile("cp.async.wait_group 2;" ::: "memory")
#define CP_WAIT1()  asm volatile("cp.async.wait_group 1;" ::: "memory")
#define CP_WAIT0()  asm volatile("cp.async.wait_group 0;" ::: "memory")

__device__ __forceinline__ void ldm4(uint32_t* f, uint32_t a) {
    asm volatile("ldmatrix.sync.aligned.m8n8.x4.shared.b16 {%0,%1,%2,%3}, [%4];"
        : "=r"(f[0]), "=r"(f[1]), "=r"(f[2]), "=r"(f[3]) : "r"(a));
}
__device__ __forceinline__ void ldm4t(uint32_t* f, uint32_t a) {
    asm volatile("ldmatrix.sync.aligned.m8n8.x4.trans.shared.b16 {%0,%1,%2,%3}, [%4];"
        : "=r"(f[0]), "=r"(f[1]), "=r"(f[2]), "=r"(f[3]) : "r"(a));
}
__device__ __forceinline__ void mma16(float* c, const uint32_t* a, uint32_t b0, uint32_t b1) {
    asm volatile("mma.sync.aligned.m16n8k16.row.col.f32.f16.f16.f32 "
        "{%0,%1,%2,%3},{%4,%5,%6,%7},{%8,%9},{%0,%1,%2,%3};"
        : "+f"(c[0]), "+f"(c[1]), "+f"(c[2]), "+f"(c[3])
        : "r"(a[0]), "r"(a[1]), "r"(a[2]), "r"(a[3]), "r"(b0), "r"(b1));
}
__device__ __forceinline__ uint32_t swz(int row, int ch) {
    return (uint32_t)(row * 64) + (uint32_t)((ch ^ ((row >> 1) & 3)) << 4);
}
__device__ __forceinline__ uint32_t swz8(int row, int ch) {
    return (uint32_t)(row * 128) + (uint32_t)((ch ^ (row & 7)) << 4);
}

// ===== Weight transpose+convert: W[z][K][N] fp32 -> o[z][N][K] fp16 =====
__global__ void wconv_t_kernel(const float* __restrict__ W,
    __half* __restrict__ o, int K, int N)
{
    __shared__ float t[32][33];
    size_t ls = (size_t)blockIdx.z * K * N;
    const float* w = W + ls;
    int k0 = blockIdx.y * 32, n0 = blockIdx.x * 32;
    int tx = threadIdx.x, ty = threadIdx.y;
    for (int i = ty; i < 32; i += 8)
        t[i][tx] = w[(size_t)(k0 + i) * N + n0 + tx];
    __syncthreads();
    int tid = ty * 32 + tx;
    int c = tid & 7, i = tid >> 3;
    uint2 u;
    u.x = pack_f16(t[4*c + 0][i], t[4*c + 1][i]);
    u.y = pack_f16(t[4*c + 2][i], t[4*c + 3][i]);
    *(uint2*)(o + ls + (size_t)(n0 + i) * K + k0 + 4*c) = u;
}

__global__ __launch_bounds__(256) void wconv_kernel(const float* __restrict__ W,
    __half* __restrict__ o, int n4)
{
    int t = blockIdx.x * 256 + threadIdx.x;
    if (t >= n4) return;
    float4 v = *(const float4*)(W + (size_t)t * 4);
    uint2 u;
    u.x = pack_f16(v.x, v.y);
    u.y = pack_f16(v.z, v.w);
    *(uint2*)(o + (size_t)t * 4) = u;
}

// ===== Fixation gather -> fp16 hi/lo =====
__global__ __launch_bounds__(256) void gather_kernel(
    const float* __restrict__ px, const int* __restrict__ fix,
    __half* __restrict__ ph, __half* __restrict__ pl)
{
    int t = blockIdx.x * 256 + threadIdx.x;
    if (t >= MPAT * DD) return;
    int d = t % DD, row = t / DD;
    int b = row / NTOK, n = row % NTOK;
    int fx = fix[(b * NTOK + n) * 2 + 0];
    int fy = fix[(b * NTOK + n) * 2 + 1];
    int c = d >> 8, rem = d & 255, i = rem >> 4, j = rem & 15;
    bool valid = (fx >= 0) && (fy >= 0);
    int top  = min(max(fy - 8, 0), 208);
    int left = min(max(fx - 8, 0), 208);
    float v = 0.f;
    if (valid) v = px[(((size_t)b * 3 + c) * 224 + (top + i)) * 224 + (left + j)];
    __half h, l; split_f16(v, h, l);
    ph[t] = h; pl[t] = l;
}

__global__ __launch_bounds__(256) void cls_init_kernel(
    const float* __restrict__ ct, const float* __restrict__ pos, float* __restrict__ x)
{
    int t = blockIdx.x * 256 + threadIdx.x;
    if (t >= BB * DD) return;
    x[(size_t)(t / DD) * SS * DD + (t % DD)] = ct[t % DD] + pos[t % DD];
}

// ===== HMMA split-fp16 GEMM (2-term), templated <NG, NT> =====
// CTA 128 x (16*NG). NT threads = NT/32 warps (4 m x NT/128 n), warp tile 32x64.
// NG=8/NT=256: 2 CTA/SM, split-K capable.  NG=16/NT=512: 1 CTA/SM, TN=256.
// 4-stage cp.async.
#define OAL 8192
#define OBS 16384

#define EPI_BIAS     0
#define EPI_RES      1
#define EPI_GELU     2
#define EPI_PATCH    3
#define EPI_QKV      4
#define EPI_RES_ATOM 5

template<int NG, int NT>
__device__ __forceinline__ void load_stage(uint32_t sbase,
    const __half* Ah, const __half* Al, const __half* B,
    int m0, int n0, int K, int k0, int Mv, int tid)
{
    #pragma unroll
    for (int g = 0; g < 512 / NT; g++) {      // A: 128 rows x 4 chunks (hi+lo)
        int idx = tid + g * NT;
        int row = idx >> 2, ch = idx & 3;
        uint32_t so = swz(row, ch);
        int ra = m0 + row;
        int rc = ra < Mv ? ra : (Mv - 1);
        size_t ga = (size_t)rc * K + k0 + ch * 8;
        cpa16(sbase + so, Ah + ga);
        cpa16(sbase + OAL + so, Al + ga);
    }
    #pragma unroll
    for (int g = 0; g < (NG * 64) / NT; g++) { // B: 16*NG rows x 4 chunks (single)
        int idx = tid + g * NT;
        int row = idx >> 2, ch = idx & 3;
        uint32_t so = swz(row, ch);
        size_t gb = (size_t)(n0 + row) * K + k0 + ch * 8;
        cpa16(sbase + OBS + so, B + gb);
    }
}

template<int NG, int NT>
__global__ __launch_bounds__(NT, (NG == 8) ? 2 : 1) void gemm_hmma(
    const __half* __restrict__ Ah, const __half* __restrict__ Al,
    const __half* __restrict__ B,
    float* __restrict__ Cf, __half* __restrict__ Coh, __half* __restrict__ Col,
    int Mv, int N, int K, int Ksub,
    const float* __restrict__ bias, const float* __restrict__ pos, int mode)
{
    constexpr int STG = 16384 + NG * 1024;
    extern __shared__ char smem[];
    uint32_t sb = s2u(smem);
    int tid = threadIdx.x, wid = tid >> 5, lane = tid & 31;
    const int m0 = blockIdx.y * 128;
    const int n0 = blockIdx.x * (16 * NG);
    const int kBase = blockIdx.z * Ksub;
    const int wm = wid & 3, wn = wid >> 2;   // 4 m-warps x (NT/128) n-warps

    float acc[2][8][4];
    #pragma unroll
    for (int a = 0; a < 2; a++)
        #pragma unroll
        for (int b = 0; b < 8; b++)
            #pragma unroll
            for (int d = 0; d < 4; d++) acc[a][b][d] = 0.f;

    const int nk = Ksub / 32;
    #pragma unroll
    for (int s = 0; s < 3; s++) {
        load_stage<NG, NT>(sb + s * STG, Ah, Al, B, m0, n0, K, kBase + s * 32, Mv, tid);
        CP_COMMIT();
    }

    const int arow_l = (lane & 15);
    const int acsel  = (lane >> 4);
    const int brow_l = (lane & 7) + ((lane >> 4) << 3);
    const int bcsel  = ((lane >> 3) & 1);

    for (int kt = 0; kt < nk; kt++) {
        CP_WAIT2();
        __syncthreads();
        if (kt + 3 < nk)
            load_stage<NG, NT>(sb + ((kt + 3) & 3) * STG, Ah, Al, B, m0, n0, K, kBase + (kt + 3) * 32, Mv, tid);
        CP_COMMIT();

        uint32_t cs = sb + (kt & 3) * STG;
        #pragma unroll
        for (int ks = 0; ks < 2; ks++) {
            int cbase = ks * 2;
            uint32_t ah[2][4], al[2][4];
            #pragma unroll
            for (int mg = 0; mg < 2; mg++) {
                int r = wm * 32 + mg * 16 + arow_l;
                uint32_t a_ad = cs + swz(r, cbase + acsel);
                ldm4(ah[mg], a_ad);
                ldm4(al[mg], a_ad + OAL);
            }
            #pragma unroll
            for (int p = 0; p < 4; p++) {
                int br = wn * 64 + p * 16 + brow_l;
                uint32_t b_ad = cs + OBS + swz(br, cbase + bcsel);
                uint32_t bq[4];
                ldm4(bq, b_ad);
                #pragma unroll
                for (int mg = 0; mg < 2; mg++) {
                    #pragma unroll
                    for (int sub = 0; sub < 2; sub++) {
                        float* C = acc[mg][p * 2 + sub];
                        mma16(C, ah[mg], bq[sub * 2], bq[sub * 2 + 1]);
                        mma16(C, al[mg], bq[sub * 2], bq[sub * 2 + 1]);
                    }
                }
            }
        }
    }

    // Epilogue
    #pragma unroll
    for (int mg = 0; mg < 2; mg++) {
        #pragma unroll
        for (int ng = 0; ng < 8; ng++) {
            int col = n0 + wn * 64 + ng * 8 + 2 * (lane & 3);
            float2 bz = *(const float2*)(bias + col);
            #pragma unroll
            for (int half = 0; half < 2; half++) {
                int row = m0 + wm * 32 + mg * 16 + (lane >> 2) + half * 8;
                if (row >= Mv) continue;
                float a0 = acc[mg][ng][half * 2 + 0];
                float a1 = acc[mg][ng][half * 2 + 1];
                if (mode == EPI_RES_ATOM) {
                    if (blockIdx.z == 0) { a0 += bz.x; a1 += bz.y; }
                    atomicAdd(Cf + (size_t)row * N + col,     a0);
                    atomicAdd(Cf + (size_t)row * N + col + 1, a1);
                    continue;
                }
                float v0 = a0 + bz.x;
                float v1 = a1 + bz.y;
                if (mode == EPI_BIAS) {
                    *(float2*)(Cf + (size_t)row * N + col) = make_float2(v0, v1);
                } else if (mode == EPI_RES) {
                    float2 o = *(const float2*)(Cf + (size_t)row * N + col);
                    o.x += v0; o.y += v1;
                    *(float2*)(Cf + (size_t)row * N + col) = o;
                } else if (mode == EPI_GELU) {
                    v0 = 0.5f * v0 * (1.f + erff(v0 * 0.70710678118654752f));
                    v1 = 0.5f * v1 * (1.f + erff(v1 * 0.70710678118654752f));
                    uint32_t ul;
                    uint32_t uh = split_pack(v0, v1, ul);
                    *(uint32_t*)(Coh + (size_t)row * N + col) = uh;
                    *(uint32_t*)(Col + (size_t)row * N + col) = ul;
                } else if (mode == EPI_QKV) {
                    float sc = (col < DD) ? 0.125f : 1.0f;
                    v0 *= sc; v1 *= sc;
                    uint32_t ul;
                    uint32_t uh = split_pack(v0, v1, ul);
                    *(uint32_t*)(Coh + (size_t)row * N + col) = uh;
                    *(uint32_t*)(Col + (size_t)row * N + col) = ul;
                } else { // EPI_PATCH
                    int b = row / NTOK, n = row % NTOK;
                    float2 pz = *(const float2*)(pos + (size_t)(n + 1) * DD + col);
                    v0 += pz.x; v1 += pz.y;
                    *(float2*)(Cf + (size_t)(b * SS + n + 1) * DD + col) = make_float2(v0, v1);
                }
            }
        }
    }
}

// ===== Flash attention (2-term split-fp16; Q/P split, K/V single) =====
#define FQH 0
#define FQL 16384
#define FK  32768
#define FV  59392
#define FSMEM 86016

__global__ __launch_bounds__(256) void flash_kernel(
    const __half* __restrict__ QKVh, const __half* __restrict__ QKVl,
    __half* __restrict__ Oh, __half* __restrict__ Ol)
{
    extern __shared__ char smem[];
    uint32_t sb = s2u(smem);
    int tid = threadIdx.x, wid = tid >> 5, lane = tid & 31;
    int bh = blockIdx.y, b = bh / NHH, h = bh % NHH;
    int qt = blockIdx.x * 128;
    const int R3D = 3 * DD;
    const int hoff = h * HDD;

    #pragma unroll
    for (int i = 0; i < 4; i++) {
        int idx = tid + i * 256;
        int row = idx >> 3, ch = idx & 7;
        int r = qt + row; if (r > SS - 1) r = SS - 1;
        size_t g = (size_t)(b * SS + r) * R3D + hoff + ch * 8;
        uint32_t so = swz8(row, ch);
        cpa16(sb + FQH + so, QKVh + g);
        cpa16(sb + FQL + so, QKVl + g);
    }
    #pragma unroll
    for (int i = 0; i < 7; i++) {
        int idx = tid + i * 256;
        if (idx < 1664) {
            int row = idx >> 3, ch = idx & 7;
            int r = row > SS - 1 ? SS - 1 : row;
            size_t g = (size_t)(b * SS + r) * R3D + DD + hoff + ch * 8;
            cpa16(sb + FK + swz8(row, ch), QKVh + g);
        }
    }
    CP_COMMIT();
    #pragma unroll
    for (int i = 0; i < 7; i++) {
        int idx = tid + i * 256;
        if (idx < 1664) {
            int row = idx >> 3, ch = idx & 7;
            int r = row > SS - 1 ? SS - 1 : row;
            size_t g = (size_t)(b * SS + r) * R3D + 2 * DD + hoff + ch * 8;
            cpa16(sb + FV + swz8(row, ch), QKVh + g);
        }
    }
    CP_COMMIT();
    CP_WAIT1();
    __syncthreads();

    float S[26][4];
    #pragma unroll
    for (int t = 0; t < 26; t++)
        #pragma unroll
        for (int e = 0; e < 4; e++) S[t][e] = 0.f;

    const int arow = lane & 15, acsel = lane >> 4;
    const int brow = (lane & 7) + ((lane >> 4) << 3), bcsel = (lane >> 3) & 1;

    #pragma unroll
    for (int ks = 0; ks < 4; ks++) {
        uint32_t qh[4], ql[4];
        uint32_t qa = sb + FQH + swz8(wid * 16 + arow, ks * 2 + acsel);
        ldm4(qh, qa);
        ldm4(ql, qa + (FQL - FQH));
        #pragma unroll
        for (int p = 0; p < 13; p++) {
            uint32_t kq[4];
            ldm4(kq, sb + FK + swz8(p * 16 + brow, ks * 2 + bcsel));
            #pragma unroll
            for (int sub = 0; sub < 2; sub++) {
                float* C = S[p * 2 + sub];
                mma16(C, qh, kq[sub * 2], kq[sub * 2 + 1]);
                mma16(C, ql, kq[sub * 2], kq[sub * 2 + 1]);
            }
        }
    }

    #pragma unroll
    for (int t = 24; t < 26; t++) {
        #pragma unroll
        for (int e = 0; e < 2; e++) {
            int colv = 8 * t + 2 * (lane & 3) + e;
            if (colv >= SS) { S[t][e] = -1e30f; S[t][2 + e] = -1e30f; }
        }
    }

    float m0 = -1e30f, m1 = -1e30f;
    #pragma unroll
    for (int t = 0; t < 26; t++) {
        m0 = fmaxf(m0, fmaxf(S[t][0], S[t][1]));
        m1 = fmaxf(m1, fmaxf(S[t][2], S[t][3]));
    }
    m0 = fmaxf(m0, __shfl_xor_sync(0xffffffff, m0, 1));
    m0 = fmaxf(m0, __shfl_xor_sync(0xffffffff, m0, 2));
    m1 = fmaxf(m1, __shfl_xor_sync(0xffffffff, m1, 1));
    m1 = fmaxf(m1, __shfl_xor_sync(0xffffffff, m1, 2));
    float s0 = 0.f, s1 = 0.f;
    #pragma unroll
    for (int t = 0; t < 26; t++) {
        S[t][0] = __expf(S[t][0] - m0); S[t][1] = __expf(S[t][1] - m0);
        S[t][2] = __expf(S[t][2] - m1); S[t][3] = __expf(S[t][3] - m1);
        s0 += S[t][0] + S[t][1];
        s1 += S[t][2] + S[t][3];
    }
    s0 += __shfl_xor_sync(0xffffffff, s0, 1);
    s0 += __shfl_xor_sync(0xffffffff, s0, 2);
    s1 += __shfl_xor_sync(0xffffffff, s1, 1);
    s1 += __shfl_xor_sync(0xffffffff, s1, 2);
    float inv0 = 1.f / s0, inv1 = 1.f / s1;

    CP_WAIT0();
    __syncthreads();

    float Cv[8][4];
    #pragma unroll
    for (int d = 0; d < 8; d++)
        #pragma unroll
        for (int e = 0; e < 4; e++) Cv[d][e] = 0.f;

    const int jr = (lane & 7) + (((lane >> 3) & 1) << 3);
    const int csel = lane >> 4;

    #pragma unroll
    for (int t = 0; t < 13; t++) {
        uint32_t aph[4], apl[4];
        aph[0] = split_pack(S[2*t][0],   S[2*t][1],   apl[0]);
        aph[1] = split_pack(S[2*t][2],   S[2*t][3],   apl[1]);
        aph[2] = split_pack(S[2*t+1][0], S[2*t+1][1], apl[2]);
        aph[3] = split_pack(S[2*t+1][2], S[2*t+1][3], apl[3]);
        #pragma unroll
        for (int dt = 0; dt < 4; dt++) {
            uint32_t vq[4];
            ldm4t(vq, sb + FV + swz8(t * 16 + jr, dt * 2 + csel));
            #pragma unroll
            for (int sub = 0; sub < 2; sub++) {
                float* C = Cv[dt * 2 + sub];
                mma16(C, aph, vq[sub * 2], vq[sub * 2 + 1]);
                mma16(C, apl, vq[sub * 2], vq[sub * 2 + 1]);
            }
        }
    }

    int r0 = qt + wid * 16 + (lane >> 2);
    int r1 = r0 + 8;
    #pragma unroll
    for (int nt = 0; nt < 8; nt++) {
        int col = hoff + nt * 8 + 2 * (lane & 3);
        if (r0 < SS) {
            uint32_t ul;
            uint32_t uh = split_pack(Cv[nt][0] * inv0, Cv[nt][1] * inv0, ul);
            size_t o = (size_t)(b * SS + r0) * DD + col;
            *(uint32_t*)(Oh + o) = uh;
            *(uint32_t*)(Ol + o) = ul;
        }
        if (r1 < SS) {
            uint32_t ul;
            uint32_t uh = split_pack(Cv[nt][2] * inv1, Cv[nt][3] * inv1, ul);
            size_t o = (size_t)(b * SS + r1) * DD + col;
            *(uint32_t*)(Oh + o) = uh;
            *(uint32_t*)(Ol + o) = ul;
        }
    }
}

// ===== LayerNorm: warp per row, fp16 hi/lo output =====
__global__ __launch_bounds__(256) void ln_f16_kernel(
    const float* __restrict__ x, __half* __restrict__ oh, __half* __restrict__ ol,
    const float* __restrict__ g, const float* __restrict__ bb)
{
    int wid = threadIdx.x >> 5, lane = threadIdx.x & 31;
    int row = blockIdx.x * 8 + wid;
    const float* xr = x + (size_t)row * DD;
    float4 v[6];
    float sum = 0.f;
    #pragma unroll
    for (int j = 0; j < 6; j++) {
        v[j] = *(const float4*)(xr + j * 128 + lane * 4);
        sum += v[j].x + v[j].y + v[j].z + v[j].w;
    }
    #pragma unroll
    for (int o = 16; o > 0; o >>= 1) sum += __shfl_xor_sync(0xffffffff, sum, o);
    float mu = sum * (1.f / 768.f);
    float var = 0.f;
    #pragma unroll
    for (int j = 0; j < 6; j++) {
        v[j].x -= mu; v[j].y -= mu; v[j].z -= mu; v[j].w -= mu;
        var += v[j].x * v[j].x + v[j].y * v[j].y + v[j].z * v[j].z + v[j].w * v[j].w;
    }
    #pragma unroll
    for (int o = 16; o > 0; o >>= 1) var += __shfl_xor_sync(0xffffffff, var, o);
    float rs = rsqrtf(var * (1.f / 768.f) + 1e-12f);
    size_t base = (size_t)row * DD;
    #pragma unroll
    for (int j = 0; j < 6; j++) {
        int col = j * 128 + lane * 4;
        float4 gg = *(const float4*)(g + col);
        float4 bz = *(const float4*)(bb + col);
        float y0 = v[j].x * rs * gg.x + bz.x;
        float y1 = v[j].y * rs * gg.y + bz.y;
        float y2 = v[j].z * rs * gg.z + bz.z;
        float y3 = v[j].w * rs * gg.w + bz.w;
        uint2 uh, ul;
        uh.x = split_pack(y0, y1, ul.x);
        uh.y = split_pack(y2, y3, ul.y);
        *(uint2*)(oh + base + col) = uh;
        *(uint2*)(ol + base + col) = ul;
    }
}

__device__ __forceinline__ float block_reduce_sum(float v, float* red) {
    int tid = threadIdx.x;
    red[tid] = v; __syncthreads();
    #pragma unroll
    for (int s = 128; s > 0; s >>= 1) { if (tid < s) red[tid] += red[tid + s]; __syncthreads(); }
    float r = red[0]; __syncthreads();
    return r;
}

__global__ __launch_bounds__(256) void ln_f32_kernel(
    const float* __restrict__ x, float* __restrict__ o,
    const float* __restrict__ g, const float* __restrict__ bb, int rowstep)
{
    __shared__ float red[256];
    const float* xr = x + (size_t)blockIdx.x * rowstep * DD;
    float* orow = o + (size_t)blockIdx.x * DD;
    int tid = threadIdx.x;
    float v0 = xr[tid], v1 = xr[tid + 256], v2 = xr[tid + 512];
    float mu = block_reduce_sum(v0 + v1 + v2, red) * (1.f / 768.f);
    float d0 = v0 - mu, d1 = v1 - mu, d2 = v2 - mu;
    float var = block_reduce_sum(d0*d0 + d1*d1 + d2*d2, red) * (1.f / 768.f);
    float rs = rsqrtf(var + 1e-12f);
    orow[tid]     = d0*rs*g[tid]     + bb[tid];
    orow[tid+256] = d1*rs*g[tid+256] + bb[tid+256];
    orow[tid+512] = d2*rs*g[tid+512] + bb[tid+512];
}

__global__ __launch_bounds__(256) void cls_head_kernel(
    const float* __restrict__ xc, const float* __restrict__ w,
    const float* __restrict__ bias, float* __restrict__ out)
{
    int wid = (blockIdx.x * 256 + threadIdx.x) >> 5;
    int lane = threadIdx.x & 31;
    if (wid >= BB * NLAB) return;
    int b = wid / NLAB, n = wid % NLAB;
    const float* xr = xc + (size_t)b * DD;
    const float* wr = w + (size_t)n * DD;
    float s = 0.f;
    for (int k = lane * 4; k < DD; k += 128) {
        float4 a = *(const float4*)(xr + k);
        float4 c = *(const float4*)(wr + k);
        s += a.x*c.x + a.y*c.y + a.z*c.z + a.w*c.w;
    }
    #pragma unroll
    for (int o = 16; o > 0; o >>= 1) s += __shfl_xor_sync(0xffffffff, s, o);
    if (lane == 0) out[(size_t)b * NLAB + n] = s + bias[n];
}

// ===== Host =====
extern "C" void kernel_launch(void* const* d_in, const int* in_sizes, int n_in,
                              void* d_out, int out_size) {
    const float* px      = (const float*)d_in[0];
    const int*   fix     = (const int*)  d_in[1];
    const float* patch_w = (const float*)d_in[2];
    const float* patch_b = (const float*)d_in[3];
    const float* cls_tok = (const float*)d_in[4];
    const float* pos_emb = (const float*)d_in[5];
    const float* ln1_g   = (const float*)d_in[6];
    const float* ln1_b   = (const float*)d_in[7];
    const float* wqkv    = (const float*)d_in[8];
    const float* bqkv    = (const float*)d_in[9];
    const float* wo      = (const float*)d_in[10];
    const float* bo      = (const float*)d_in[11];
    const float* ln2_g   = (const float*)d_in[12];
    const float* ln2_b   = (const float*)d_in[13];
    const float* w1      = (const float*)d_in[14];
    const float* b1      = (const float*)d_in[15];
    const float* w2      = (const float*)d_in[16];
    const float* b2      = (const float*)d_in[17];
    const float* lnf_g   = (const float*)d_in[18];
    const float* lnf_b   = (const float*)d_in[19];
    const float* cls_w   = (const float*)d_in[20];
    const float* cls_b   = (const float*)d_in[21];
    float* out = (float*)d_out;

    __half *ph,*pl,*hh,*hl,*oh,*ol,*mh,*ml,*qkvh,*qkvl;
    __half *wq,*wop,*w1p,*w2p,*pwp;
    float *x,*clsb;
    cudaGetSymbolAddress((void**)&ph, g_ph);   cudaGetSymbolAddress((void**)&pl, g_pl);
    cudaGetSymbolAddress((void**)&hh, g_hh);   cudaGetSymbolAddress((void**)&hl, g_hl);
    cudaGetSymbolAddress((void**)&oh, g_oh);   cudaGetSymbolAddress((void**)&ol, g_ol);
    cudaGetSymbolAddress((void**)&mh, g_mh);   cudaGetSymbolAddress((void**)&ml, g_ml);
    cudaGetSymbolAddress((void**)&qkvh, g_qkvh); cudaGetSymbolAddress((void**)&qkvl, g_qkvl);
    cudaGetSymbolAddress((void**)&wq, g_wqkv);
    cudaGetSymbolAddress((void**)&wop, g_wo);
    cudaGetSymbolAddress((void**)&w1p, g_w1);
    cudaGetSymbolAddress((void**)&w2p, g_w2);
    cudaGetSymbolAddress((void**)&pwp, g_pw);
    cudaGetSymbolAddress((void**)&x, g_x);     cudaGetSymbolAddress((void**)&clsb, g_cls);

    const int SM8  = 4 * (16384 + 8 * 1024);    // 98304
    const int SM16 = 4 * (16384 + 16 * 1024);   // 131072
    cudaFuncSetAttribute((const void*)gemm_hmma<8, 256>,  cudaFuncAttributeMaxDynamicSharedMemorySize, SM8);
    cudaFuncSetAttribute((const void*)gemm_hmma<16, 512>, cudaFuncAttributeMaxDynamicSharedMemorySize, SM16);
    cudaFuncSetAttribute(flash_kernel, cudaFuncAttributeMaxDynamicSharedMemorySize, FSMEM);

    static cudaStream_t s2 = nullptr;
    static cudaEvent_t evF = nullptr, evJ = nullptr;
    if (s2 == nullptr) {
        cudaStreamCreateWithFlags(&s2, cudaStreamNonBlocking);
        cudaEventCreateWithFlags(&evF, cudaEventDisableTiming);
        cudaEventCreateWithFlags(&evJ, cudaEventDisableTiming);
    }

    // Fork: weight conversions on s2 overlap gather/patch-embed
    cudaEventRecord(evF, 0);
    cudaStreamWaitEvent(s2, evF, 0);
    wconv_t_kernel<<<dim3(3*DD/32, DD/32, LLAY), dim3(32,8), 0, s2>>>(wqkv, wq, DD, 3*DD);
    wconv_t_kernel<<<dim3(DD/32,   DD/32, LLAY), dim3(32,8), 0, s2>>>(wo,   wop, DD, DD);
    wconv_t_kernel<<<dim3(FF/32,   DD/32, LLAY), dim3(32,8), 0, s2>>>(w1,   w1p, DD, FF);
    wconv_t_kernel<<<dim3(DD/32,   FF/32, LLAY), dim3(32,8), 0, s2>>>(w2,   w2p, FF, DD);
    cudaEventRecord(evJ, s2);

    gather_kernel<<<(MPAT*DD + 255)/256, 256>>>(px, fix, ph, pl);
    wconv_kernel<<<(DD*DD/4 + 255)/256, 256>>>(patch_w, pwp, DD*DD/4);
    cls_init_kernel<<<(BB*DD + 255)/256, 256>>>(cls_tok, pos_emb, x);
    gemm_hmma<16, 512><<<dim3(DD/256, (MPAT + 127)/128, 1), 512, SM16>>>(
        ph, pl, pwp, x, nullptr, nullptr, MPAT, DD, DD, DD, patch_b, pos_emb, EPI_PATCH);

    cudaStreamWaitEvent(0, evJ, 0);

    const int gM = (MROWS + 127) / 128;  // 50
    for (int l = 0; l < LLAY; l++) {
        ln_f16_kernel<<<MROWS/8, 256>>>(x, hh, hl, ln1_g + l*DD, ln1_b + l*DD);
        gemm_hmma<16, 512><<<dim3(3*DD/256, gM, 1), 512, SM16>>>(
            hh, hl, wq + (size_t)l*3*DD*DD,
            nullptr, qkvh, qkvl, MROWS, 3*DD, DD, DD, bqkv + (size_t)l*3*DD, nullptr, EPI_QKV);
        flash_kernel<<<dim3(2, BHN), 256, FSMEM>>>(qkvh, qkvl, oh, ol);
        gemm_hmma<8, 256><<<dim3(DD/128, gM, 2), 256, SM8>>>(
            oh, ol, wop + (size_t)l*DD*DD,
            x, nullptr, nullptr, MROWS, DD, DD, DD/2, bo + (size_t)l*DD, nullptr, EPI_RES_ATOM);
        ln_f16_kernel<<<MROWS/8, 256>>>(x, hh, hl, ln2_g + l*DD, ln2_b + l*DD);
        gemm_hmma<16, 512><<<dim3(FF/256, gM, 1), 512, SM16>>>(
            hh, hl, w1p + (size_t)l*FF*DD,
            nullptr, mh, ml, MROWS, FF, DD, DD, b1 + (size_t)l*FF, nullptr, EPI_GELU);
        gemm_hmma<8, 256><<<dim3(DD/128, gM, 2), 256, SM8>>>(
            mh, ml, w2p + (size_t)l*DD*FF,
            x, nullptr, nullptr, MROWS, DD, FF, FF/2, b2 + (size_t)l*DD, nullptr, EPI_RES_ATOM);
    }

    ln_f32_kernel<<<BB, 256>>>(x, clsb, lnf_g, lnf_b, SS);
    cls_head_kernel<<<(BB*NLAB*32 + 255)/256, 256>>>(clsb, cls_w, cls_b, out);
}

// round 15
// speedup vs baseline: 1.2028x; 1.2028x over previous
#include <cuda_runtime.h>
#include <cuda_fp16.h>
#include <math.h>
#include <stdint.h>

#define BB   32
#define SS   197
#define NTOK 196
#define DD   768
#define NHH  12
#define HDD  64
#define FF   3072
#define LLAY 12
#define NLAB 1000
#define MROWS (BB*SS)
#define MPAT  (BB*NTOK)
#define BHN   (BB*NHH)

// ===== Scratch =====
__device__ __half g_ph[MPAT * DD], g_pl[MPAT * DD];
__device__ __half g_hh[MROWS * DD], g_hl[MROWS * DD];
__device__ __half g_oh[MROWS * DD], g_ol[MROWS * DD];
__device__ __half g_mh[MROWS * FF];
__device__ __half g_qkvh[MROWS * 3 * DD], g_qkvl[MROWS * 3 * DD];
__device__ __half g_wqkv[LLAY*3*DD*DD];
__device__ __half g_wo[LLAY*DD*DD];
__device__ __half g_w1[LLAY*FF*DD];
__device__ __half g_w2[LLAY*DD*FF];
__device__ __half g_pw[DD * DD];
__device__ float g_x[MROWS * DD];
__device__ float g_cls[BB * DD];

// ===== helpers =====
__device__ __forceinline__ uint32_t s2u(const void* p) {
    uint32_t a;
    asm("{ .reg .u64 t; cvta.to.shared.u64 t, %1; cvt.u32.u64 %0, t; }" : "=r"(a) : "l"(p));
    return a;
}
__device__ __forceinline__ void split_f16(float v, __half& h, __half& l) {
    h = __float2half_rn(v);
    l = __float2half_rn(v - __half2float(h));
}
__device__ __forceinline__ uint32_t pack_f16(float v0, float v1) {
    return ((uint32_t)__half_as_ushort(__float2half_rn(v1)) << 16)
         | __half_as_ushort(__float2half_rn(v0));
}
__device__ __forceinline__ uint32_t split_pack(float v0, float v1, uint32_t& lo) {
    __half h0, l0, h1, l1;
    split_f16(v0, h0, l0); split_f16(v1, h1, l1);
    lo = ((uint32_t)__half_as_ushort(l1) << 16) | __half_as_ushort(l0);
    return ((uint32_t)__half_as_ushort(h1) << 16) | __half_as_ushort(h0);
}
__device__ __forceinline__ void cpa16(uint32_t s, const void* g) {
    asm volatile("cp.async.cg.shared.global [%0], [%1], 16;"
        :: "r"(s), "l"(g) : "memory");
}
#define CP_COMMIT() asm volatile("cp.async.commit_group;" ::: "memory")
#define CP_WAIT2()  asm volatile("cp.async.wait_group 2;" ::: "memory")
#define CP_WAIT1()  asm volatile("cp.async.wait_group 1;" ::: "memory")
#define CP_WAIT0()  asm volatile("cp.async.wait_group 0;" ::: "memory")

__device__ __forceinline__ void ldm4(uint32_t* f, uint32_t a) {
    asm volatile("ldmatrix.sync.aligned.m8n8.x4.shared.b16 {%0,%1,%2,%3}, [%4];"
        : "=r"(f[0]), "=r"(f[1]), "=r"(f[2]), "=r"(f[3]) : "r"(a));
}
__device__ __forceinline__ void ldm4t(uint32_t* f, uint32_t a) {
    asm volatile("ldmatrix.sync.aligned.m8n8.x4.trans.shared.b16 {%0,%1,%2,%3}, [%4];"
        : "=r"(f[0]), "=r"(f[1]), "=r"(f[2]), "=r"(f[3]) : "r"(a));
}
__device__ __forceinline__ void mma16(float* c, const uint32_t* a, uint32_t b0, uint32_t b1) {
    asm volatile("mma.sync.aligned.m16n8k16.row.col.f32.f16.f16.f32 "
        "{%0,%1,%2,%3},{%4,%5,%6,%7},{%8,%9},{%0,%1,%2,%3};"
        : "+f"(c[0]), "+f"(c[1]), "+f"(c[2]), "+f"(c[3])
        : "r"(a[0]), "r"(a[1]), "r"(a[2]), "r"(a[3]), "r"(b0), "r"(b1));
}
__device__ __forceinline__ uint32_t swz(int row, int ch) {
    return (uint32_t)(row * 64) + (uint32_t)((ch ^ ((row >> 1) & 3)) << 4);
}
__device__ __forceinline__ uint32_t swz8(int row, int ch) {
    return (uint32_t)(row * 128) + (uint32_t)((ch ^ (row & 7)) << 4);
}

// ===== Weight transpose+convert: W[z][K][N] fp32 -> o[z][N][K] fp16 =====
__global__ void wconv_t_kernel(const float* __restrict__ W,
    __half* __restrict__ o, int K, int N)
{
    __shared__ float t[32][33];
    size_t ls = (size_t)blockIdx.z * K * N;
    const float* w = W + ls;
    int k0 = blockIdx.y * 32, n0 = blockIdx.x * 32;
    int tx = threadIdx.x, ty = threadIdx.y;
    for (int i = ty; i < 32; i += 8)
        t[i][tx] = w[(size_t)(k0 + i) * N + n0 + tx];
    __syncthreads();
    int tid = ty * 32 + tx;
    int c = tid & 7, i = tid >> 3;
    uint2 u;
    u.x = pack_f16(t[4*c + 0][i], t[4*c + 1][i]);
    u.y = pack_f16(t[4*c + 2][i], t[4*c + 3][i]);
    *(uint2*)(o + ls + (size_t)(n0 + i) * K + k0 + 4*c) = u;
}

__global__ __launch_bounds__(256) void wconv_kernel(const float* __restrict__ W,
    __half* __restrict__ o, int n4)
{
    int t = blockIdx.x * 256 + threadIdx.x;
    if (t >= n4) return;
    float4 v = *(const float4*)(W + (size_t)t * 4);
    uint2 u;
    u.x = pack_f16(v.x, v.y);
    u.y = pack_f16(v.z, v.w);
    *(uint2*)(o + (size_t)t * 4) = u;
}

// ===== Fixation gather -> fp16 hi/lo =====
__global__ __launch_bounds__(256) void gather_kernel(
    const float* __restrict__ px, const int* __restrict__ fix,
    __half* __restrict__ ph, __half* __restrict__ pl)
{
    int t = blockIdx.x * 256 + threadIdx.x;
    if (t >= MPAT * DD) return;
    int d = t % DD, row = t / DD;
    int b = row / NTOK, n = row % NTOK;
    int fx = fix[(b * NTOK + n) * 2 + 0];
    int fy = fix[(b * NTOK + n) * 2 + 1];
    int c = d >> 8, rem = d & 255, i = rem >> 4, j = rem & 15;
    bool valid = (fx >= 0) && (fy >= 0);
    int top  = min(max(fy - 8, 0), 208);
    int left = min(max(fx - 8, 0), 208);
    float v = 0.f;
    if (valid) v = px[(((size_t)b * 3 + c) * 224 + (top + i)) * 224 + (left + j)];
    __half h, l; split_f16(v, h, l);
    ph[t] = h; pl[t] = l;
}

__global__ __launch_bounds__(256) void cls_init_kernel(
    const float* __restrict__ ct, const float* __restrict__ pos, float* __restrict__ x)
{
    int t = blockIdx.x * 256 + threadIdx.x;
    if (t >= BB * DD) return;
    x[(size_t)(t / DD) * SS * DD + (t % DD)] = ct[t % DD] + pos[t % DD];
}

// ===== HMMA fp16 GEMM, TN=128, split-K via blockIdx.z, templated SPLITA =====
// CTA 128x128, BK=32, 256 threads (4x2 warps, warp tile 32x64), 4-stage, 2 CTA/SM.
// SPLITA=true: A is hi/lo split, 2-term MMA.  SPLITA=false: single fp16 A, 1-term.
#define OAL 8192
#define OBS 16384
#define STG 24576
#define GSMEM (4*STG)

#define EPI_BIAS     0
#define EPI_RES      1
#define EPI_GELU     2
#define EPI_PATCH    3
#define EPI_QKV      4
#define EPI_RES_ATOM 5

template<bool SPLITA>
__device__ __forceinline__ void load_stage(uint32_t sbase,
    const __half* Ah, const __half* Al, const __half* B,
    int m0, int n0, int K, int k0, int Mv, int tid)
{
    #pragma unroll
    for (int g = 0; g < 2; g++) {       // A: 128 rows x 4 chunks
        int idx = tid + g * 256;
        int row = idx >> 2, ch = idx & 3;
        uint32_t so = swz(row, ch);
        int ra = m0 + row;
        int rc = ra < Mv ? ra : (Mv - 1);
        size_t ga = (size_t)rc * K + k0 + ch * 8;
        cpa16(sbase + so, Ah + ga);
        if (SPLITA) cpa16(sbase + OAL + so, Al + ga);
    }
    #pragma unroll
    for (int g = 0; g < 2; g++) {       // B: 128 rows x 4 chunks (single)
        int idx = tid + g * 256;
        int row = idx >> 2, ch = idx & 3;
        uint32_t so = swz(row, ch);
        size_t gb = (size_t)(n0 + row) * K + k0 + ch * 8;
        cpa16(sbase + OBS + so, B + gb);
    }
}

template<bool SPLITA>
__global__ __launch_bounds__(256, 2) void gemm_hmma(
    const __half* __restrict__ Ah, const __half* __restrict__ Al,
    const __half* __restrict__ B,
    float* __restrict__ Cf, __half* __restrict__ Coh, __half* __restrict__ Col,
    int Mv, int N, int K, int Ksub,
    const float* __restrict__ bias, const float* __restrict__ pos, int mode)
{
    extern __shared__ char smem[];
    uint32_t sb = s2u(smem);
    int tid = threadIdx.x, wid = tid >> 5, lane = tid & 31;
    const int m0 = blockIdx.y * 128;
    const int n0 = blockIdx.x * 128;
    const int kBase = blockIdx.z * Ksub;
    const int wm = wid & 3, wn = wid >> 2;

    float acc[2][8][4];
    #pragma unroll
    for (int a = 0; a < 2; a++)
        #pragma unroll
        for (int b = 0; b < 8; b++)
            #pragma unroll
            for (int d = 0; d < 4; d++) acc[a][b][d] = 0.f;

    const int nk = Ksub / 32;
    #pragma unroll
    for (int s = 0; s < 3; s++) {
        load_stage<SPLITA>(sb + s * STG, Ah, Al, B, m0, n0, K, kBase + s * 32, Mv, tid);
        CP_COMMIT();
    }

    const int arow_l = (lane & 15);
    const int acsel  = (lane >> 4);
    const int brow_l = (lane & 7) + ((lane >> 4) << 3);
    const int bcsel  = ((lane >> 3) & 1);

    for (int kt = 0; kt < nk; kt++) {
        CP_WAIT2();
        __syncthreads();
        if (kt + 3 < nk)
            load_stage<SPLITA>(sb + ((kt + 3) & 3) * STG, Ah, Al, B, m0, n0, K, kBase + (kt + 3) * 32, Mv, tid);
        CP_COMMIT();

        uint32_t cs = sb + (kt & 3) * STG;
        #pragma unroll
        for (int ks = 0; ks < 2; ks++) {
            int cbase = ks * 2;
            uint32_t ah[2][4], al[2][4];
            #pragma unroll
            for (int mg = 0; mg < 2; mg++) {
                int r = wm * 32 + mg * 16 + arow_l;
                uint32_t a_ad = cs + swz(r, cbase + acsel);
                ldm4(ah[mg], a_ad);
                if (SPLITA) ldm4(al[mg], a_ad + OAL);
            }
            #pragma unroll
            for (int p = 0; p < 4; p++) {
                int br = wn * 64 + p * 16 + brow_l;
                uint32_t b_ad = cs + OBS + swz(br, cbase + bcsel);
                uint32_t bq[4];
                ldm4(bq, b_ad);
                #pragma unroll
                for (int mg = 0; mg < 2; mg++) {
                    #pragma unroll
                    for (int sub = 0; sub < 2; sub++) {
                        float* C = acc[mg][p * 2 + sub];
                        mma16(C, ah[mg], bq[sub * 2], bq[sub * 2 + 1]);
                        if (SPLITA) mma16(C, al[mg], bq[sub * 2], bq[sub * 2 + 1]);
                    }
                }
            }
        }
    }

    // Epilogue
    #pragma unroll
    for (int mg = 0; mg < 2; mg++) {
        #pragma unroll
        for (int ng = 0; ng < 8; ng++) {
            int col = n0 + wn * 64 + ng * 8 + 2 * (lane & 3);
            float2 bz = *(const float2*)(bias + col);
            #pragma unroll
            for (int half = 0; half < 2; half++) {
                int row = m0 + wm * 32 + mg * 16 + (lane >> 2) + half * 8;
                if (row >= Mv) continue;
                float a0 = acc[mg][ng][half * 2 + 0];
                float a1 = acc[mg][ng][half * 2 + 1];
                if (mode == EPI_RES_ATOM) {
                    if (blockIdx.z == 0) { a0 += bz.x; a1 += bz.y; }
                    atomicAdd(Cf + (size_t)row * N + col,     a0);
                    atomicAdd(Cf + (size_t)row * N + col + 1, a1);
                    continue;
                }
                float v0 = a0 + bz.x;
                float v1 = a1 + bz.y;
                if (mode == EPI_BIAS) {
                    *(float2*)(Cf + (size_t)row * N + col) = make_float2(v0, v1);
                } else if (mode == EPI_RES) {
                    float2 o = *(const float2*)(Cf + (size_t)row * N + col);
                    o.x += v0; o.y += v1;
                    *(float2*)(Cf + (size_t)row * N + col) = o;
                } else if (mode == EPI_GELU) {
                    // single-fp16 GELU output (act quantization, MLP2 is 1-term)
                    v0 = 0.5f * v0 * (1.f + erff(v0 * 0.70710678118654752f));
                    v1 = 0.5f * v1 * (1.f + erff(v1 * 0.70710678118654752f));
                    *(uint32_t*)(Coh + (size_t)row * N + col) = pack_f16(v0, v1);
                } else if (mode == EPI_QKV) {
                    float sc = (col < DD) ? 0.125f : 1.0f;
                    v0 *= sc; v1 *= sc;
                    uint32_t ul;
                    uint32_t uh = split_pack(v0, v1, ul);
                    *(uint32_t*)(Coh + (size_t)row * N + col) = uh;
                    *(uint32_t*)(Col + (size_t)row * N + col) = ul;
                } else { // EPI_PATCH
                    int b = row / NTOK, n = row % NTOK;
                    float2 pz = *(const float2*)(pos + (size_t)(n + 1) * DD + col);
                    v0 += pz.x; v1 += pz.y;
                    *(float2*)(Cf + (size_t)(b * SS + n + 1) * DD + col) = make_float2(v0, v1);
                }
            }
        }
    }
}

// ===== Flash attention (2-term split-fp16; Q/P split, K/V single) =====
#define FQH 0
#define FQL 16384
#define FK  32768
#define FV  59392
#define FSMEM 86016

__global__ __launch_bounds__(256) void flash_kernel(
    const __half* __restrict__ QKVh, const __half* __restrict__ QKVl,
    __half* __restrict__ Oh, __half* __restrict__ Ol)
{
    extern __shared__ char smem[];
    uint32_t sb = s2u(smem);
    int tid = threadIdx.x, wid = tid >> 5, lane = tid & 31;
    int bh = blockIdx.y, b = bh / NHH, h = bh % NHH;
    int qt = blockIdx.x * 128;
    const int R3D = 3 * DD;
    const int hoff = h * HDD;

    #pragma unroll
    for (int i = 0; i < 4; i++) {
        int idx = tid + i * 256;
        int row = idx >> 3, ch = idx & 7;
        int r = qt + row; if (r > SS - 1) r = SS - 1;
        size_t g = (size_t)(b * SS + r) * R3D + hoff + ch * 8;
        uint32_t so = swz8(row, ch);
        cpa16(sb + FQH + so, QKVh + g);
        cpa16(sb + FQL + so, QKVl + g);
    }
    #pragma unroll
    for (int i = 0; i < 7; i++) {
        int idx = tid + i * 256;
        if (idx < 1664) {
            int row = idx >> 3, ch = idx & 7;
            int r = row > SS - 1 ? SS - 1 : row;
            size_t g = (size_t)(b * SS + r) * R3D + DD + hoff + ch * 8;
            cpa16(sb + FK + swz8(row, ch), QKVh + g);
        }
    }
    CP_COMMIT();
    #pragma unroll
    for (int i = 0; i < 7; i++) {
        int idx = tid + i * 256;
        if (idx < 1664) {
            int row = idx >> 3, ch = idx & 7;
            int r = row > SS - 1 ? SS - 1 : row;
            size_t g = (size_t)(b * SS + r) * R3D + 2 * DD + hoff + ch * 8;
            cpa16(sb + FV + swz8(row, ch), QKVh + g);
        }
    }
    CP_COMMIT();
    CP_WAIT1();
    __syncthreads();

    float S[26][4];
    #pragma unroll
    for (int t = 0; t < 26; t++)
        #pragma unroll
        for (int e = 0; e < 4; e++) S[t][e] = 0.f;

    const int arow = lane & 15, acsel = lane >> 4;
    const int brow = (lane & 7) + ((lane >> 4) << 3), bcsel = (lane >> 3) & 1;

    #pragma unroll
    for (int ks = 0; ks < 4; ks++) {
        uint32_t qh[4], ql[4];
        uint32_t qa = sb + FQH + swz8(wid * 16 + arow, ks * 2 + acsel);
        ldm4(qh, qa);
        ldm4(ql, qa + (FQL - FQH));
        #pragma unroll
        for (int p = 0; p < 13; p++) {
            uint32_t kq[4];
            ldm4(kq, sb + FK + swz8(p * 16 + brow, ks * 2 + bcsel));
            #pragma unroll
            for (int sub = 0; sub < 2; sub++) {
                float* C = S[p * 2 + sub];
                mma16(C, qh, kq[sub * 2], kq[sub * 2 + 1]);
                mma16(C, ql, kq[sub * 2], kq[sub * 2 + 1]);
            }
        }
    }

    #pragma unroll
    for (int t = 24; t < 26; t++) {
        #pragma unroll
        for (int e = 0; e < 2; e++) {
            int colv = 8 * t + 2 * (lane & 3) + e;
            if (colv >= SS) { S[t][e] = -1e30f; S[t][2 + e] = -1e30f; }
        }
    }

    float m0 = -1e30f, m1 = -1e30f;
    #pragma unroll
    for (int t = 0; t < 26; t++) {
        m0 = fmaxf(m0, fmaxf(S[t][0], S[t][1]));
        m1 = fmaxf(m1, fmaxf(S[t][2], S[t][3]));
    }
    m0 = fmaxf(m0, __shfl_xor_sync(0xffffffff, m0, 1));
    m0 = fmaxf(m0, __shfl_xor_sync(0xffffffff, m0, 2));
    m1 = fmaxf(m1, __shfl_xor_sync(0xffffffff, m1, 1));
    m1 = fmaxf(m1, __shfl_xor_sync(0xffffffff, m1, 2));
    float s0 = 0.f, s1 = 0.f;
    #pragma unroll
    for (int t = 0; t < 26; t++) {
        S[t][0] = __expf(S[t][0] - m0); S[t][1] = __expf(S[t][1] - m0);
        S[t][2] = __expf(S[t][2] - m1); S[t][3] = __expf(S[t][3] - m1);
        s0 += S[t][0] + S[t][1];
        s1 += S[t][2] + S[t][3];
    }
    s0 += __shfl_xor_sync(0xffffffff, s0, 1);
    s0 += __shfl_xor_sync(0xffffffff, s0, 2);
    s1 += __shfl_xor_sync(0xffffffff, s1, 1);
    s1 += __shfl_xor_sync(0xffffffff, s1, 2);
    float inv0 = 1.f / s0, inv1 = 1.f / s1;

    CP_WAIT0();
    __syncthreads();

    float Cv[8][4];
    #pragma unroll
    for (int d = 0; d < 8; d++)
        #pragma unroll
        for (int e = 0; e < 4; e++) Cv[d][e] = 0.f;

    const int jr = (lane & 7) + (((lane >> 3) & 1) << 3);
    const int csel = lane >> 4;

    #pragma unroll
    for (int t = 0; t < 13; t++) {
        uint32_t aph[4], apl[4];
        aph[0] = split_pack(S[2*t][0],   S[2*t][1],   apl[0]);
        aph[1] = split_pack(S[2*t][2],   S[2*t][3],   apl[1]);
        aph[2] = split_pack(S[2*t+1][0], S[2*t+1][1], apl[2]);
        aph[3] = split_pack(S[2*t+1][2], S[2*t+1][3], apl[3]);
        #pragma unroll
        for (int dt = 0; dt < 4; dt++) {
            uint32_t vq[4];
            ldm4t(vq, sb + FV + swz8(t * 16 + jr, dt * 2 + csel));
            #pragma unroll
            for (int sub = 0; sub < 2; sub++) {
                float* C = Cv[dt * 2 + sub];
                mma16(C, aph, vq[sub * 2], vq[sub * 2 + 1]);
                mma16(C, apl, vq[sub * 2], vq[sub * 2 + 1]);
            }
        }
    }

    int r0 = qt + wid * 16 + (lane >> 2);
    int r1 = r0 + 8;
    #pragma unroll
    for (int nt = 0; nt < 8; nt++) {
        int col = hoff + nt * 8 + 2 * (lane & 3);
        if (r0 < SS) {
            uint32_t ul;
            uint32_t uh = split_pack(Cv[nt][0] * inv0, Cv[nt][1] * inv0, ul);
            size_t o = (size_t)(b * SS + r0) * DD + col;
            *(uint32_t*)(Oh + o) = uh;
            *(uint32_t*)(Ol + o) = ul;
        }
        if (r1 < SS) {
            uint32_t ul;
            uint32_t uh = split_pack(Cv[nt][2] * inv1, Cv[nt][3] * inv1, ul);
            size_t o = (size_t)(b * SS + r1) * DD + col;
            *(uint32_t*)(Oh + o) = uh;
            *(uint32_t*)(Ol + o) = ul;
        }
    }
}

// ===== LayerNorm: warp per row, fp16 hi/lo output =====
__global__ __launch_bounds__(256) void ln_f16_kernel(
    const float* __restrict__ x, __half* __restrict__ oh, __half* __restrict__ ol,
    const float* __restrict__ g, const float* __restrict__ bb)
{
    int wid = threadIdx.x >> 5, lane = threadIdx.x & 31;
    int row = blockIdx.x * 8 + wid;
    const float* xr = x + (size_t)row * DD;
    float4 v[6];
    float sum = 0.f;
    #pragma unroll
    for (int j = 0; j < 6; j++) {
        v[j] = *(const float4*)(xr + j * 128 + lane * 4);
        sum += v[j].x + v[j].y + v[j].z + v[j].w;
    }
    #pragma unroll
    for (int o = 16; o > 0; o >>= 1) sum += __shfl_xor_sync(0xffffffff, sum, o);
    float mu = sum * (1.f / 768.f);
    float var = 0.f;
    #pragma unroll
    for (int j = 0; j < 6; j++) {
        v[j].x -= mu; v[j].y -= mu; v[j].z -= mu; v[j].w -= mu;
        var += v[j].x * v[j].x + v[j].y * v[j].y + v[j].z * v[j].z + v[j].w * v[j].w;
    }
    #pragma unroll
    for (int o = 16; o > 0; o >>= 1) var += __shfl_xor_sync(0xffffffff, var, o);
    float rs = rsqrtf(var * (1.f / 768.f) + 1e-12f);
    size_t base = (size_t)row * DD;
    #pragma unroll
    for (int j = 0; j < 6; j++) {
        int col = j * 128 + lane * 4;
        float4 gg = *(const float4*)(g + col);
        float4 bz = *(const float4*)(bb + col);
        float y0 = v[j].x * rs * gg.x + bz.x;
        float y1 = v[j].y * rs * gg.y + bz.y;
        float y2 = v[j].z * rs * gg.z + bz.z;
        float y3 = v[j].w * rs * gg.w + bz.w;
        uint2 uh, ul;
        uh.x = split_pack(y0, y1, ul.x);
        uh.y = split_pack(y2, y3, ul.y);
        *(uint2*)(oh + base + col) = uh;
        *(uint2*)(ol + base + col) = ul;
    }
}

__device__ __forceinline__ float block_reduce_sum(float v, float* red) {
    int tid = threadIdx.x;
    red[tid] = v; __syncthreads();
    #pragma unroll
    for (int s = 128; s > 0; s >>= 1) { if (tid < s) red[tid] += red[tid + s]; __syncthreads(); }
    float r = red[0]; __syncthreads();
    return r;
}

__global__ __launch_bounds__(256) void ln_f32_kernel(
    const float* __restrict__ x, float* __restrict__ o,
    const float* __restrict__ g, const float* __restrict__ bb, int rowstep)
{
    __shared__ float red[256];
    const float* xr = x + (size_t)blockIdx.x * rowstep * DD;
    float* orow = o + (size_t)blockIdx.x * DD;
    int tid = threadIdx.x;
    float v0 = xr[tid], v1 = xr[tid + 256], v2 = xr[tid + 512];
    float mu = block_reduce_sum(v0 + v1 + v2, red) * (1.f / 768.f);
    float d0 = v0 - mu, d1 = v1 - mu, d2 = v2 - mu;
    float var = block_reduce_sum(d0*d0 + d1*d1 + d2*d2, red) * (1.f / 768.f);
    float rs = rsqrtf(var + 1e-12f);
    orow[tid]     = d0*rs*g[tid]     + bb[tid];
    orow[tid+256] = d1*rs*g[tid+256] + bb[tid+256];
    orow[tid+512] = d2*rs*g[tid+512] + bb[tid+512];
}

__global__ __launch_bounds__(256) void cls_head_kernel(
    const float* __restrict__ xc, const float* __restrict__ w,
    const float* __restrict__ bias, float* __restrict__ out)
{
    int wid = (blockIdx.x * 256 + threadIdx.x) >> 5;
    int lane = threadIdx.x & 31;
    if (wid >= BB * NLAB) return;
    int b = wid / NLAB, n = wid % NLAB;
    const float* xr = xc + (size_t)b * DD;
    const float* wr = w + (size_t)n * DD;
    float s = 0.f;
    for (int k = lane * 4; k < DD; k += 128) {
        float4 a = *(const float4*)(xr + k);
        float4 c = *(const float4*)(wr + k);
        s += a.x*c.x + a.y*c.y + a.z*c.z + a.w*c.w;
    }
    #pragma unroll
    for (int o = 16; o > 0; o >>= 1) s += __shfl_xor_sync(0xffffffff, s, o);
    if (lane == 0) out[(size_t)b * NLAB + n] = s + bias[n];
}

// ===== Host =====
extern "C" void kernel_launch(void* const* d_in, const int* in_sizes, int n_in,
                              void* d_out, int out_size) {
    const float* px      = (const float*)d_in[0];
    const int*   fix     = (const int*)  d_in[1];
    const float* patch_w = (const float*)d_in[2];
    const float* patch_b = (const float*)d_in[3];
    const float* cls_tok = (const float*)d_in[4];
    const float* pos_emb = (const float*)d_in[5];
    const float* ln1_g   = (const float*)d_in[6];
    const float* ln1_b   = (const float*)d_in[7];
    const float* wqkv    = (const float*)d_in[8];
    const float* bqkv    = (const float*)d_in[9];
    const float* wo      = (const float*)d_in[10];
    const float* bo      = (const float*)d_in[11];
    const float* ln2_g   = (const float*)d_in[12];
    const float* ln2_b   = (const float*)d_in[13];
    const float* w1      = (const float*)d_in[14];
    const float* b1      = (const float*)d_in[15];
    const float* w2      = (const float*)d_in[16];
    const float* b2      = (const float*)d_in[17];
    const float* lnf_g   = (const float*)d_in[18];
    const float* lnf_b   = (const float*)d_in[19];
    const float* cls_w   = (const float*)d_in[20];
    const float* cls_b   = (const float*)d_in[21];
    float* out = (float*)d_out;

    __half *ph,*pl,*hh,*hl,*oh,*ol,*mh,*qkvh,*qkvl;
    __half *wq,*wop,*w1p,*w2p,*pwp;
    float *x,*clsb;
    cudaGetSymbolAddress((void**)&ph, g_ph);   cudaGetSymbolAddress((void**)&pl, g_pl);
    cudaGetSymbolAddress((void**)&hh, g_hh);   cudaGetSymbolAddress((void**)&hl, g_hl);
    cudaGetSymbolAddress((void**)&oh, g_oh);   cudaGetSymbolAddress((void**)&ol, g_ol);
    cudaGetSymbolAddress((void**)&mh, g_mh);
    cudaGetSymbolAddress((void**)&qkvh, g_qkvh); cudaGetSymbolAddress((void**)&qkvl, g_qkvl);
    cudaGetSymbolAddress((void**)&wq, g_wqkv);
    cudaGetSymbolAddress((void**)&wop, g_wo);
    cudaGetSymbolAddress((void**)&w1p, g_w1);
    cudaGetSymbolAddress((void**)&w2p, g_w2);
    cudaGetSymbolAddress((void**)&pwp, g_pw);
    cudaGetSymbolAddress((void**)&x, g_x);     cudaGetSymbolAddress((void**)&clsb, g_cls);

    cudaFuncSetAttribute((const void*)gemm_hmma<true>,  cudaFuncAttributeMaxDynamicSharedMemorySize, GSMEM);
    cudaFuncSetAttribute((const void*)gemm_hmma<false>, cudaFuncAttributeMaxDynamicSharedMemorySize, GSMEM);
    cudaFuncSetAttribute(flash_kernel, cudaFuncAttributeMaxDynamicSharedMemorySize, FSMEM);

    static cudaStream_t s2 = nullptr;
    static cudaEvent_t evF = nullptr, evJ = nullptr;
    if (s2 == nullptr) {
        cudaStreamCreateWithFlags(&s2, cudaStreamNonBlocking);
        cudaEventCreateWithFlags(&evF, cudaEventDisableTiming);
        cudaEventCreateWithFlags(&evJ, cudaEventDisableTiming);
    }

    // Fork: weight conversions on s2 overlap gather/patch-embed
    cudaEventRecord(evF, 0);
    cudaStreamWaitEvent(s2, evF, 0);
    wconv_t_kernel<<<dim3(3*DD/32, DD/32, LLAY), dim3(32,8), 0, s2>>>(wqkv, wq, DD, 3*DD);
    wconv_t_kernel<<<dim3(DD/32,   DD/32, LLAY), dim3(32,8), 0, s2>>>(wo,   wop, DD, DD);
    wconv_t_kernel<<<dim3(FF/32,   DD/32, LLAY), dim3(32,8), 0, s2>>>(w1,   w1p, DD, FF);
    wconv_t_kernel<<<dim3(DD/32,   FF/32, LLAY), dim3(32,8), 0, s2>>>(w2,   w2p, FF, DD);
    cudaEventRecord(evJ, s2);

    gather_kernel<<<(MPAT*DD + 255)/256, 256>>>(px, fix, ph, pl);
    wconv_kernel<<<(DD*DD/4 + 255)/256, 256>>>(patch_w, pwp, DD*DD/4);
    cls_init_kernel<<<(BB*DD + 255)/256, 256>>>(cls_tok, pos_emb, x);
    gemm_hmma<true><<<dim3(DD/128, (MPAT + 127)/128, 1), 256, GSMEM>>>(
        ph, pl, pwp, x, nullptr, nullptr, MPAT, DD, DD, DD, patch_b, pos_emb, EPI_PATCH);

    cudaStreamWaitEvent(0, evJ, 0);

    const int gM = (MROWS + 127) / 128;  // 50
    for (int l = 0; l < LLAY; l++) {
        ln_f16_kernel<<<MROWS/8, 256>>>(x, hh, hl, ln1_g + l*DD, ln1_b + l*DD);
        gemm_hmma<true><<<dim3(3*DD/128, gM, 1), 256, GSMEM>>>(
            hh, hl, wq + (size_t)l*3*DD*DD,
            nullptr, qkvh, qkvl, MROWS, 3*DD, DD, DD, bqkv + (size_t)l*3*DD, nullptr, EPI_QKV);
        flash_kernel<<<dim3(2, BHN), 256, FSMEM>>>(qkvh, qkvl, oh, ol);
        gemm_hmma<true><<<dim3(DD/128, gM, 2), 256, GSMEM>>>(
            oh, ol, wop + (size_t)l*DD*DD,
            x, nullptr, nullptr, MROWS, DD, DD, DD/2, bo + (size_t)l*DD, nullptr, EPI_RES_ATOM);
        ln_f16_kernel<<<MROWS/8, 256>>>(x, hh, hl, ln2_g + l*DD, ln2_b + l*DD);
        gemm_hmma<true><<<dim3(FF/128, gM, 1), 256, GSMEM>>>(
            hh, hl, w1p + (size_t)l*FF*DD,
            nullptr, mh, nullptr, MROWS, FF, DD, DD, b1 + (size_t)l*FF, nullptr, EPI_GELU);
        gemm_hmma<false><<<dim3(DD/128, gM, 2), 256, GSMEM>>>(
            mh, nullptr, w2p + (size_t)l*DD*FF,
            x, nullptr, nullptr, MROWS, DD, FF, FF/2, b2 + (size_t)l*DD, nullptr, EPI_RES_ATOM);
    }

    ln_f32_kernel<<<BB, 256>>>(x, clsb, lnf_g, lnf_b, SS);
    cls_head_kernel<<<(BB*NLAB*32 + 255)/256, 256>>>(clsb, cls_w, cls_b, out);
}

// round 16
// speedup vs baseline: 1.3689x; 1.1380x over previous
#include <cuda_runtime.h>
#include <cuda_fp16.h>
#include <math.h>
#include <stdint.h>

#define BB   32
#define SS   197
#define NTOK 196
#define DD   768
#define NHH  12
#define HDD  64
#define FF   3072
#define LLAY 12
#define NLAB 1000
#define MROWS (BB*SS)
#define MPAT  (BB*NTOK)
#define BHN   (BB*NHH)

// ===== Scratch =====
__device__ __half g_ph[MPAT * DD], g_pl[MPAT * DD];
__device__ __half g_hh[MROWS * DD], g_hl[MROWS * DD];
__device__ __half g_oh[MROWS * DD], g_ol[MROWS * DD];
__device__ __half g_mh[MROWS * FF];
__device__ __half g_qkvh[MROWS * 3 * DD], g_qkvl[MROWS * 3 * DD];
__device__ __half g_wqkv[LLAY*3*DD*DD];
__device__ __half g_wo[LLAY*DD*DD];
__device__ __half g_w1[LLAY*FF*DD];
__device__ __half g_w2[LLAY*DD*FF];
__device__ __half g_pw[DD * DD];
__device__ float g_x[MROWS * DD];
__device__ float g_cls[BB * DD];

// ===== helpers =====
__device__ __forceinline__ uint32_t s2u(const void* p) {
    uint32_t a;
    asm("{ .reg .u64 t; cvta.to.shared.u64 t, %1; cvt.u32.u64 %0, t; }" : "=r"(a) : "l"(p));
    return a;
}
__device__ __forceinline__ void split_f16(float v, __half& h, __half& l) {
    h = __float2half_rn(v);
    l = __float2half_rn(v - __half2float(h));
}
__device__ __forceinline__ uint32_t pack_f16(float v0, float v1) {
    return ((uint32_t)__half_as_ushort(__float2half_rn(v1)) << 16)
         | __half_as_ushort(__float2half_rn(v0));
}
__device__ __forceinline__ uint32_t split_pack(float v0, float v1, uint32_t& lo) {
    __half h0, l0, h1, l1;
    split_f16(v0, h0, l0); split_f16(v1, h1, l1);
    lo = ((uint32_t)__half_as_ushort(l1) << 16) | __half_as_ushort(l0);
    return ((uint32_t)__half_as_ushort(h1) << 16) | __half_as_ushort(h0);
}
__device__ __forceinline__ void cpa16(uint32_t s, const void* g) {
    asm volatile("cp.async.cg.shared.global [%0], [%1], 16;"
        :: "r"(s), "l"(g) : "memory");
}
#define CP_COMMIT() asm volatile("cp.async.commit_group;" ::: "memory")
#define CP_WAIT2()  asm volatile("cp.async.wait_group 2;" ::: "memory")
#define CP_WAIT1()  asm volatile("cp.async.wait_group 1;" ::: "memory")
#define CP_WAIT0()  asm volatile("cp.async.wait_group 0;" ::: "memory")

__device__ __forceinline__ void ldm4(uint32_t* f, uint32_t a) {
    asm volatile("ldmatrix.sync.aligned.m8n8.x4.shared.b16 {%0,%1,%2,%3}, [%4];"
        : "=r"(f[0]), "=r"(f[1]), "=r"(f[2]), "=r"(f[3]) : "r"(a));
}
__device__ __forceinline__ void ldm4t(uint32_t* f, uint32_t a) {
    asm volatile("ldmatrix.sync.aligned.m8n8.x4.trans.shared.b16 {%0,%1,%2,%3}, [%4];"
        : "=r"(f[0]), "=r"(f[1]), "=r"(f[2]), "=r"(f[3]) : "r"(a));
}
__device__ __forceinline__ void mma16(float* c, const uint32_t* a, uint32_t b0, uint32_t b1) {
    asm volatile("mma.sync.aligned.m16n8k16.row.col.f32.f16.f16.f32 "
        "{%0,%1,%2,%3},{%4,%5,%6,%7},{%8,%9},{%0,%1,%2,%3};"
        : "+f"(c[0]), "+f"(c[1]), "+f"(c[2]), "+f"(c[3])
        : "r"(a[0]), "r"(a[1]), "r"(a[2]), "r"(a[3]), "r"(b0), "r"(b1));
}
__device__ __forceinline__ uint32_t swz(int row, int ch) {
    return (uint32_t)(row * 64) + (uint32_t)((ch ^ ((row >> 1) & 3)) << 4);
}
__device__ __forceinline__ uint32_t swz8(int row, int ch) {
    return (uint32_t)(row * 128) + (uint32_t)((ch ^ (row & 7)) << 4);
}

// ===== Weight transpose+convert: W[z][K][N] fp32 -> o[z][N][K] fp16 =====
__global__ void wconv_t_kernel(const float* __restrict__ W,
    __half* __restrict__ o, int K, int N)
{
    __shared__ float t[32][33];
    size_t ls = (size_t)blockIdx.z * K * N;
    const float* w = W + ls;
    int k0 = blockIdx.y * 32, n0 = blockIdx.x * 32;
    int tx = threadIdx.x, ty = threadIdx.y;
    for (int i = ty; i < 32; i += 8)
        t[i][tx] = w[(size_t)(k0 + i) * N + n0 + tx];
    __syncthreads();
    int tid = ty * 32 + tx;
    int c = tid & 7, i = tid >> 3;
    uint2 u;
    u.x = pack_f16(t[4*c + 0][i], t[4*c + 1][i]);
    u.y = pack_f16(t[4*c + 2][i], t[4*c + 3][i]);
    *(uint2*)(o + ls + (size_t)(n0 + i) * K + k0 + 4*c) = u;
}

__global__ __launch_bounds__(256) void wconv_kernel(const float* __restrict__ W,
    __half* __restrict__ o, int n4)
{
    int t = blockIdx.x * 256 + threadIdx.x;
    if (t >= n4) return;
    float4 v = *(const float4*)(W + (size_t)t * 4);
    uint2 u;
    u.x = pack_f16(v.x, v.y);
    u.y = pack_f16(v.z, v.w);
    *(uint2*)(o + (size_t)t * 4) = u;
}

// ===== Fixation gather -> fp16 hi/lo =====
__global__ __launch_bounds__(256) void gather_kernel(
    const float* __restrict__ px, const int* __restrict__ fix,
    __half* __restrict__ ph, __half* __restrict__ pl)
{
    int t = blockIdx.x * 256 + threadIdx.x;
    if (t >= MPAT * DD) return;
    int d = t % DD, row = t / DD;
    int b = row / NTOK, n = row % NTOK;
    int fx = fix[(b * NTOK + n) * 2 + 0];
    int fy = fix[(b * NTOK + n) * 2 + 1];
    int c = d >> 8, rem = d & 255, i = rem >> 4, j = rem & 15;
    bool valid = (fx >= 0) && (fy >= 0);
    int top  = min(max(fy - 8, 0), 208);
    int left = min(max(fx - 8, 0), 208);
    float v = 0.f;
    if (valid) v = px[(((size_t)b * 3 + c) * 224 + (top + i)) * 224 + (left + j)];
    __half h, l; split_f16(v, h, l);
    ph[t] = h; pl[t] = l;
}

__global__ __launch_bounds__(256) void cls_init_kernel(
    const float* __restrict__ ct, const float* __restrict__ pos, float* __restrict__ x)
{
    int t = blockIdx.x * 256 + threadIdx.x;
    if (t >= BB * DD) return;
    x[(size_t)(t / DD) * SS * DD + (t % DD)] = ct[t % DD] + pos[t % DD];
}

// ===== HMMA fp16 GEMM, TN=128, split-K via blockIdx.z, templated SPLITA =====
// CTA 128x128, BK=32, 256 threads (4x2 warps, warp tile 32x64), 4-stage, 2 CTA/SM.
#define OAL 8192
#define OBS 16384
#define STG 24576
#define GSMEM (4*STG)

#define EPI_BIAS     0
#define EPI_RES      1
#define EPI_GELU     2
#define EPI_PATCH    3
#define EPI_QKV      4
#define EPI_RES_ATOM 5

template<bool SPLITA>
__device__ __forceinline__ void load_stage(uint32_t sbase,
    const __half* Ah, const __half* Al, const __half* B,
    int m0, int n0, int K, int k0, int Mv, int tid)
{
    #pragma unroll
    for (int g = 0; g < 2; g++) {       // A: 128 rows x 4 chunks
        int idx = tid + g * 256;
        int row = idx >> 2, ch = idx & 3;
        uint32_t so = swz(row, ch);
        int ra = m0 + row;
        int rc = ra < Mv ? ra : (Mv - 1);
        size_t ga = (size_t)rc * K + k0 + ch * 8;
        cpa16(sbase + so, Ah + ga);
        if (SPLITA) cpa16(sbase + OAL + so, Al + ga);
    }
    #pragma unroll
    for (int g = 0; g < 2; g++) {       // B: 128 rows x 4 chunks (single)
        int idx = tid + g * 256;
        int row = idx >> 2, ch = idx & 3;
        uint32_t so = swz(row, ch);
        size_t gb = (size_t)(n0 + row) * K + k0 + ch * 8;
        cpa16(sbase + OBS + so, B + gb);
    }
}

template<bool SPLITA>
__global__ __launch_bounds__(256, 2) void gemm_hmma(
    const __half* __restrict__ Ah, const __half* __restrict__ Al,
    const __half* __restrict__ B,
    float* __restrict__ Cf, __half* __restrict__ Coh, __half* __restrict__ Col,
    int Mv, int N, int K, int Ksub,
    const float* __restrict__ bias, const float* __restrict__ pos, int mode)
{
    extern __shared__ char smem[];
    uint32_t sb = s2u(smem);
    int tid = threadIdx.x, wid = tid >> 5, lane = tid & 31;
    const int m0 = blockIdx.y * 128;
    const int n0 = blockIdx.x * 128;
    const int kBase = blockIdx.z * Ksub;
    const int wm = wid & 3, wn = wid >> 2;

    float acc[2][8][4];
    #pragma unroll
    for (int a = 0; a < 2; a++)
        #pragma unroll
        for (int b = 0; b < 8; b++)
            #pragma unroll
            for (int d = 0; d < 4; d++) acc[a][b][d] = 0.f;

    const int nk = Ksub / 32;
    #pragma unroll
    for (int s = 0; s < 3; s++) {
        load_stage<SPLITA>(sb + s * STG, Ah, Al, B, m0, n0, K, kBase + s * 32, Mv, tid);
        CP_COMMIT();
    }

    const int arow_l = (lane & 15);
    const int acsel  = (lane >> 4);
    const int brow_l = (lane & 7) + ((lane >> 4) << 3);
    const int bcsel  = ((lane >> 3) & 1);

    for (int kt = 0; kt < nk; kt++) {
        CP_WAIT2();
        __syncthreads();
        if (kt + 3 < nk)
            load_stage<SPLITA>(sb + ((kt + 3) & 3) * STG, Ah, Al, B, m0, n0, K, kBase + (kt + 3) * 32, Mv, tid);
        CP_COMMIT();

        uint32_t cs = sb + (kt & 3) * STG;
        #pragma unroll
        for (int ks = 0; ks < 2; ks++) {
            int cbase = ks * 2;
            uint32_t ah[2][4], al[2][4];
            #pragma unroll
            for (int mg = 0; mg < 2; mg++) {
                int r = wm * 32 + mg * 16 + arow_l;
                uint32_t a_ad = cs + swz(r, cbase + acsel);
                ldm4(ah[mg], a_ad);
                if (SPLITA) ldm4(al[mg], a_ad + OAL);
            }
            #pragma unroll
            for (int p = 0; p < 4; p++) {
                int br = wn * 64 + p * 16 + brow_l;
                uint32_t b_ad = cs + OBS + swz(br, cbase + bcsel);
                uint32_t bq[4];
                ldm4(bq, b_ad);
                #pragma unroll
                for (int mg = 0; mg < 2; mg++) {
                    #pragma unroll
                    for (int sub = 0; sub < 2; sub++) {
                        float* C = acc[mg][p * 2 + sub];
                        mma16(C, ah[mg], bq[sub * 2], bq[sub * 2 + 1]);
                        if (SPLITA) mma16(C, al[mg], bq[sub * 2], bq[sub * 2 + 1]);
                    }
                }
            }
        }
    }

    // Epilogue
    #pragma unroll
    for (int mg = 0; mg < 2; mg++) {
        #pragma unroll
        for (int ng = 0; ng < 8; ng++) {
            int col = n0 + wn * 64 + ng * 8 + 2 * (lane & 3);
            float2 bz = *(const float2*)(bias + col);
            #pragma unroll
            for (int half = 0; half < 2; half++) {
                int row = m0 + wm * 32 + mg * 16 + (lane >> 2) + half * 8;
                if (row >= Mv) continue;
                float a0 = acc[mg][ng][half * 2 + 0];
                float a1 = acc[mg][ng][half * 2 + 1];
                if (mode == EPI_RES_ATOM) {
                    if (blockIdx.z == 0) { a0 += bz.x; a1 += bz.y; }
                    atomicAdd(Cf + (size_t)row * N + col,     a0);
                    atomicAdd(Cf + (size_t)row * N + col + 1, a1);
                    continue;
                }
                float v0 = a0 + bz.x;
                float v1 = a1 + bz.y;
                if (mode == EPI_BIAS) {
                    *(float2*)(Cf + (size_t)row * N + col) = make_float2(v0, v1);
                } else if (mode == EPI_RES) {
                    float2 o = *(const float2*)(Cf + (size_t)row * N + col);
                    o.x += v0; o.y += v1;
                    *(float2*)(Cf + (size_t)row * N + col) = o;
                } else if (mode == EPI_GELU) {
                    v0 = 0.5f * v0 * (1.f + erff(v0 * 0.70710678118654752f));
                    v1 = 0.5f * v1 * (1.f + erff(v1 * 0.70710678118654752f));
                    *(uint32_t*)(Coh + (size_t)row * N + col) = pack_f16(v0, v1);
                } else if (mode == EPI_QKV) {
                    float sc = (col < DD) ? 0.125f : 1.0f;
                    v0 *= sc; v1 *= sc;
                    uint32_t ul;
                    uint32_t uh = split_pack(v0, v1, ul);
                    *(uint32_t*)(Coh + (size_t)row * N + col) = uh;
                    *(uint32_t*)(Col + (size_t)row * N + col) = ul;
                } else { // EPI_PATCH
                    int b = row / NTOK, n = row % NTOK;
                    float2 pz = *(const float2*)(pos + (size_t)(n + 1) * DD + col);
                    v0 += pz.x; v1 += pz.y;
                    *(float2*)(Cf + (size_t)(b * SS + n + 1) * DD + col) = make_float2(v0, v1);
                }
            }
        }
    }
}

// ===== Flash attention (2-term split-fp16; Q/P split, K/V single) =====
#define FQH 0
#define FQL 16384
#define FK  32768
#define FV  59392
#define FSMEM 86016

__global__ __launch_bounds__(256) void flash_kernel(
    const __half* __restrict__ QKVh, const __half* __restrict__ QKVl,
    __half* __restrict__ Oh, __half* __restrict__ Ol)
{
    extern __shared__ char smem[];
    uint32_t sb = s2u(smem);
    int tid = threadIdx.x, wid = tid >> 5, lane = tid & 31;
    int bh = blockIdx.y, b = bh / NHH, h = bh % NHH;
    int qt = blockIdx.x * 128;
    const int R3D = 3 * DD;
    const int hoff = h * HDD;

    #pragma unroll
    for (int i = 0; i < 4; i++) {
        int idx = tid + i * 256;
        int row = idx >> 3, ch = idx & 7;
        int r = qt + row; if (r > SS - 1) r = SS - 1;
        size_t g = (size_t)(b * SS + r) * R3D + hoff + ch * 8;
        uint32_t so = swz8(row, ch);
        cpa16(sb + FQH + so, QKVh + g);
        cpa16(sb + FQL + so, QKVl + g);
    }
    #pragma unroll
    for (int i = 0; i < 7; i++) {
        int idx = tid + i * 256;
        if (idx < 1664) {
            int row = idx >> 3, ch = idx & 7;
            int r = row > SS - 1 ? SS - 1 : row;
            size_t g = (size_t)(b * SS + r) * R3D + DD + hoff + ch * 8;
            cpa16(sb + FK + swz8(row, ch), QKVh + g);
        }
    }
    CP_COMMIT();
    #pragma unroll
    for (int i = 0; i < 7; i++) {
        int idx = tid + i * 256;
        if (idx < 1664) {
            int row = idx >> 3, ch = idx & 7;
            int r = row > SS - 1 ? SS - 1 : row;
            size_t g = (size_t)(b * SS + r) * R3D + 2 * DD + hoff + ch * 8;
            cpa16(sb + FV + swz8(row, ch), QKVh + g);
        }
    }
    CP_COMMIT();
    CP_WAIT1();
    __syncthreads();

    float S[26][4];
    #pragma unroll
    for (int t = 0; t < 26; t++)
        #pragma unroll
        for (int e = 0; e < 4; e++) S[t][e] = 0.f;

    const int arow = lane & 15, acsel = lane >> 4;
    const int brow = (lane & 7) + ((lane >> 4) << 3), bcsel = (lane >> 3) & 1;

    #pragma unroll
    for (int ks = 0; ks < 4; ks++) {
        uint32_t qh[4], ql[4];
        uint32_t qa = sb + FQH + swz8(wid * 16 + arow, ks * 2 + acsel);
        ldm4(qh, qa);
        ldm4(ql, qa + (FQL - FQH));
        #pragma unroll
        for (int p = 0; p < 13; p++) {
            uint32_t kq[4];
            ldm4(kq, sb + FK + swz8(p * 16 + brow, ks * 2 + bcsel));
            #pragma unroll
            for (int sub = 0; sub < 2; sub++) {
                float* C = S[p * 2 + sub];
                mma16(C, qh, kq[sub * 2], kq[sub * 2 + 1]);
                mma16(C, ql, kq[sub * 2], kq[sub * 2 + 1]);
            }
        }
    }

    #pragma unroll
    for (int t = 24; t < 26; t++) {
        #pragma unroll
        for (int e = 0; e < 2; e++) {
            int colv = 8 * t + 2 * (lane & 3) + e;
            if (colv >= SS) { S[t][e] = -1e30f; S[t][2 + e] = -1e30f; }
        }
    }

    float m0 = -1e30f, m1 = -1e30f;
    #pragma unroll
    for (int t = 0; t < 26; t++) {
        m0 = fmaxf(m0, fmaxf(S[t][0], S[t][1]));
        m1 = fmaxf(m1, fmaxf(S[t][2], S[t][3]));
    }
    m0 = fmaxf(m0, __shfl_xor_sync(0xffffffff, m0, 1));
    m0 = fmaxf(m0, __shfl_xor_sync(0xffffffff, m0, 2));
    m1 = fmaxf(m1, __shfl_xor_sync(0xffffffff, m1, 1));
    m1 = fmaxf(m1, __shfl_xor_sync(0xffffffff, m1, 2));
    float s0 = 0.f, s1 = 0.f;
    #pragma unroll
    for (int t = 0; t < 26; t++) {
        S[t][0] = __expf(S[t][0] - m0); S[t][1] = __expf(S[t][1] - m0);
        S[t][2] = __expf(S[t][2] - m1); S[t][3] = __expf(S[t][3] - m1);
        s0 += S[t][0] + S[t][1];
        s1 += S[t][2] + S[t][3];
    }
    s0 += __shfl_xor_sync(0xffffffff, s0, 1);
    s0 += __shfl_xor_sync(0xffffffff, s0, 2);
    s1 += __shfl_xor_sync(0xffffffff, s1, 1);
    s1 += __shfl_xor_sync(0xffffffff, s1, 2);
    float inv0 = 1.f / s0, inv1 = 1.f / s1;

    CP_WAIT0();
    __syncthreads();

    float Cv[8][4];
    #pragma unroll
    for (int d = 0; d < 8; d++)
        #pragma unroll
        for (int e = 0; e < 4; e++) Cv[d][e] = 0.f;

    const int jr = (lane & 7) + (((lane >> 3) & 1) << 3);
    const int csel = lane >> 4;

    #pragma unroll
    for (int t = 0; t < 13; t++) {
        uint32_t aph[4], apl[4];
        aph[0] = split_pack(S[2*t][0],   S[2*t][1],   apl[0]);
        aph[1] = split_pack(S[2*t][2],   S[2*t][3],   apl[1]);
        aph[2] = split_pack(S[2*t+1][0], S[2*t+1][1], apl[2]);
        aph[3] = split_pack(S[2*t+1][2], S[2*t+1][3], apl[3]);
        #pragma unroll
        for (int dt = 0; dt < 4; dt++) {
            uint32_t vq[4];
            ldm4t(vq, sb + FV + swz8(t * 16 + jr, dt * 2 + csel));
            #pragma unroll
            for (int sub = 0; sub < 2; sub++) {
                float* C = Cv[dt * 2 + sub];
                mma16(C, aph, vq[sub * 2], vq[sub * 2 + 1]);
                mma16(C, apl, vq[sub * 2], vq[sub * 2 + 1]);
            }
        }
    }

    int r0 = qt + wid * 16 + (lane >> 2);
    int r1 = r0 + 8;
    #pragma unroll
    for (int nt = 0; nt < 8; nt++) {
        int col = hoff + nt * 8 + 2 * (lane & 3);
        if (r0 < SS) {
            uint32_t ul;
            uint32_t uh = split_pack(Cv[nt][0] * inv0, Cv[nt][1] * inv0, ul);
            size_t o = (size_t)(b * SS + r0) * DD + col;
            *(uint32_t*)(Oh + o) = uh;
            *(uint32_t*)(Ol + o) = ul;
        }
        if (r1 < SS) {
            uint32_t ul;
            uint32_t uh = split_pack(Cv[nt][2] * inv1, Cv[nt][3] * inv1, ul);
            size_t o = (size_t)(b * SS + r1) * DD + col;
            *(uint32_t*)(Oh + o) = uh;
            *(uint32_t*)(Ol + o) = ul;
        }
    }
}

// ===== LayerNorm: warp per row; SPLIT=true -> hi/lo, false -> single fp16 =====
template<bool SPLIT>
__global__ __launch_bounds__(256) void ln_f16_kernel(
    const float* __restrict__ x, __half* __restrict__ oh, __half* __restrict__ ol,
    const float* __restrict__ g, const float* __restrict__ bb)
{
    int wid = threadIdx.x >> 5, lane = threadIdx.x & 31;
    int row = blockIdx.x * 8 + wid;
    const float* xr = x + (size_t)row * DD;
    float4 v[6];
    float sum = 0.f;
    #pragma unroll
    for (int j = 0; j < 6; j++) {
        v[j] = *(const float4*)(xr + j * 128 + lane * 4);
        sum += v[j].x + v[j].y + v[j].z + v[j].w;
    }
    #pragma unroll
    for (int o = 16; o > 0; o >>= 1) sum += __shfl_xor_sync(0xffffffff, sum, o);
    float mu = sum * (1.f / 768.f);
    float var = 0.f;
    #pragma unroll
    for (int j = 0; j < 6; j++) {
        v[j].x -= mu; v[j].y -= mu; v[j].z -= mu; v[j].w -= mu;
        var += v[j].x * v[j].x + v[j].y * v[j].y + v[j].z * v[j].z + v[j].w * v[j].w;
    }
    #pragma unroll
    for (int o = 16; o > 0; o >>= 1) var += __shfl_xor_sync(0xffffffff, var, o);
    float rs = rsqrtf(var * (1.f / 768.f) + 1e-12f);
    size_t base = (size_t)row * DD;
    #pragma unroll
    for (int j = 0; j < 6; j++) {
        int col = j * 128 + lane * 4;
        float4 gg = *(const float4*)(g + col);
        float4 bz = *(const float4*)(bb + col);
        float y0 = v[j].x * rs * gg.x + bz.x;
        float y1 = v[j].y * rs * gg.y + bz.y;
        float y2 = v[j].z * rs * gg.z + bz.z;
        float y3 = v[j].w * rs * gg.w + bz.w;
        if (SPLIT) {
            uint2 uh, ul;
            uh.x = split_pack(y0, y1, ul.x);
            uh.y = split_pack(y2, y3, ul.y);
            *(uint2*)(oh + base + col) = uh;
            *(uint2*)(ol + base + col) = ul;
        } else {
            uint2 uh;
            uh.x = pack_f16(y0, y1);
            uh.y = pack_f16(y2, y3);
            *(uint2*)(oh + base + col) = uh;
        }
    }
}

__device__ __forceinline__ float block_reduce_sum(float v, float* red) {
    int tid = threadIdx.x;
    red[tid] = v; __syncthreads();
    #pragma unroll
    for (int s = 128; s > 0; s >>= 1) { if (tid < s) red[tid] += red[tid + s]; __syncthreads(); }
    float r = red[0]; __syncthreads();
    return r;
}

__global__ __launch_bounds__(256) void ln_f32_kernel(
    const float* __restrict__ x, float* __restrict__ o,
    const float* __restrict__ g, const float* __restrict__ bb, int rowstep)
{
    __shared__ float red[256];
    const float* xr = x + (size_t)blockIdx.x * rowstep * DD;
    float* orow = o + (size_t)blockIdx.x * DD;
    int tid = threadIdx.x;
    float v0 = xr[tid], v1 = xr[tid + 256], v2 = xr[tid + 512];
    float mu = block_reduce_sum(v0 + v1 + v2, red) * (1.f / 768.f);
    float d0 = v0 - mu, d1 = v1 - mu, d2 = v2 - mu;
    float var = block_reduce_sum(d0*d0 + d1*d1 + d2*d2, red) * (1.f / 768.f);
    float rs = rsqrtf(var + 1e-12f);
    orow[tid]     = d0*rs*g[tid]     + bb[tid];
    orow[tid+256] = d1*rs*g[tid+256] + bb[tid+256];
    orow[tid+512] = d2*rs*g[tid+512] + bb[tid+512];
}

__global__ __launch_bounds__(256) void cls_head_kernel(
    const float* __restrict__ xc, const float* __restrict__ w,
    const float* __restrict__ bias, float* __restrict__ out)
{
    int wid = (blockIdx.x * 256 + threadIdx.x) >> 5;
    int lane = threadIdx.x & 31;
    if (wid >= BB * NLAB) return;
    int b = wid / NLAB, n = wid % NLAB;
    const float* xr = xc + (size_t)b * DD;
    const float* wr = w + (size_t)n * DD;
    float s = 0.f;
    for (int k = lane * 4; k < DD; k += 128) {
        float4 a = *(const float4*)(xr + k);
        float4 c = *(const float4*)(wr + k);
        s += a.x*c.x + a.y*c.y + a.z*c.z + a.w*c.w;
    }
    #pragma unroll
    for (int o = 16; o > 0; o >>= 1) s += __shfl_xor_sync(0xffffffff, s, o);
    if (lane == 0) out[(size_t)b * NLAB + n] = s + bias[n];
}

// ===== Host =====
extern "C" void kernel_launch(void* const* d_in, const int* in_sizes, int n_in,
                              void* d_out, int out_size) {
    const float* px      = (const float*)d_in[0];
    const int*   fix     = (const int*)  d_in[1];
    const float* patch_w = (const float*)d_in[2];
    const float* patch_b = (const float*)d_in[3];
    const float* cls_tok = (const float*)d_in[4];
    const float* pos_emb = (const float*)d_in[5];
    const float* ln1_g   = (const float*)d_in[6];
    const float* ln1_b   = (const float*)d_in[7];
    const float* wqkv    = (const float*)d_in[8];
    const float* bqkv    = (const float*)d_in[9];
    const float* wo      = (const float*)d_in[10];
    const float* bo      = (const float*)d_in[11];
    const float* ln2_g   = (const float*)d_in[12];
    const float* ln2_b   = (const float*)d_in[13];
    const float* w1      = (const float*)d_in[14];
    const float* b1      = (const float*)d_in[15];
    const float* w2      = (const float*)d_in[16];
    const float* b2      = (const float*)d_in[17];
    const float* lnf_g   = (const float*)d_in[18];
    const float* lnf_b   = (const float*)d_in[19];
    const float* cls_w   = (const float*)d_in[20];
    const float* cls_b   = (const float*)d_in[21];
    float* out = (float*)d_out;

    __half *ph,*pl,*hh,*hl,*oh,*ol,*mh,*qkvh,*qkvl;
    __half *wq,*wop,*w1p,*w2p,*pwp;
    float *x,*clsb;
    cudaGetSymbolAddress((void**)&ph, g_ph);   cudaGetSymbolAddress((void**)&pl, g_pl);
    cudaGetSymbolAddress((void**)&hh, g_hh);   cudaGetSymbolAddress((void**)&hl, g_hl);
    cudaGetSymbolAddress((void**)&oh, g_oh);   cudaGetSymbolAddress((void**)&ol, g_ol);
    cudaGetSymbolAddress((void**)&mh, g_mh);
    cudaGetSymbolAddress((void**)&qkvh, g_qkvh); cudaGetSymbolAddress((void**)&qkvl, g_qkvl);
    cudaGetSymbolAddress((void**)&wq, g_wqkv);
    cudaGetSymbolAddress((void**)&wop, g_wo);
    cudaGetSymbolAddress((void**)&w1p, g_w1);
    cudaGetSymbolAddress((void**)&w2p, g_w2);
    cudaGetSymbolAddress((void**)&pwp, g_pw);
    cudaGetSymbolAddress((void**)&x, g_x);     cudaGetSymbolAddress((void**)&clsb, g_cls);

    cudaFuncSetAttribute((const void*)gemm_hmma<true>,  cudaFuncAttributeMaxDynamicSharedMemorySize, GSMEM);
    cudaFuncSetAttribute((const void*)gemm_hmma<false>, cudaFuncAttributeMaxDynamicSharedMemorySize, GSMEM);
    cudaFuncSetAttribute(flash_kernel, cudaFuncAttributeMaxDynamicSharedMemorySize, FSMEM);

    static cudaStream_t s2 = nullptr;
    static cudaEvent_t evF = nullptr, evJ = nullptr;
    if (s2 == nullptr) {
        cudaStreamCreateWithFlags(&s2, cudaStreamNonBlocking);
        cudaEventCreateWithFlags(&evF, cudaEventDisableTiming);
        cudaEventCreateWithFlags(&evJ, cudaEventDisableTiming);
    }

    // Fork: weight conversions on s2 overlap gather/patch-embed
    cudaEventRecord(evF, 0);
    cudaStreamWaitEvent(s2, evF, 0);
    wconv_t_kernel<<<dim3(3*DD/32, DD/32, LLAY), dim3(32,8), 0, s2>>>(wqkv, wq, DD, 3*DD);
    wconv_t_kernel<<<dim3(DD/32,   DD/32, LLAY), dim3(32,8), 0, s2>>>(wo,   wop, DD, DD);
    wconv_t_kernel<<<dim3(FF/32,   DD/32, LLAY), dim3(32,8), 0, s2>>>(w1,   w1p, DD, FF);
    wconv_t_kernel<<<dim3(DD/32,   FF/32, LLAY), dim3(32,8), 0, s2>>>(w2,   w2p, FF, DD);
    cudaEventRecord(evJ, s2);

    gather_kernel<<<(MPAT*DD + 255)/256, 256>>>(px, fix, ph, pl);
    wconv_kernel<<<(DD*DD/4 + 255)/256, 256>>>(patch_w, pwp, DD*DD/4);
    cls_init_kernel<<<(BB*DD + 255)/256, 256>>>(cls_tok, pos_emb, x);
    gemm_hmma<true><<<dim3(DD/128, (MPAT + 127)/128, 1), 256, GSMEM>>>(
        ph, pl, pwp, x, nullptr, nullptr, MPAT, DD, DD, DD, patch_b, pos_emb, EPI_PATCH);

    cudaStreamWaitEvent(0, evJ, 0);

    const int gM = (MROWS + 127) / 128;  // 50
    for (int l = 0; l < LLAY; l++) {
        ln_f16_kernel<true><<<MROWS/8, 256>>>(x, hh, hl, ln1_g + l*DD, ln1_b + l*DD);
        gemm_hmma<true><<<dim3(3*DD/128, gM, 1), 256, GSMEM>>>(
            hh, hl, wq + (size_t)l*3*DD*DD,
            nullptr, qkvh, qkvl, MROWS, 3*DD, DD, DD, bqkv + (size_t)l*3*DD, nullptr, EPI_QKV);
        flash_kernel<<<dim3(2, BHN), 256, FSMEM>>>(qkvh, qkvl, oh, ol);
        gemm_hmma<true><<<dim3(DD/128, gM, 2), 256, GSMEM>>>(
            oh, ol, wop + (size_t)l*DD*DD,
            x, nullptr, nullptr, MROWS, DD, DD, DD/2, bo + (size_t)l*DD, nullptr, EPI_RES_ATOM);
        ln_f16_kernel<false><<<MROWS/8, 256>>>(x, hh, nullptr, ln2_g + l*DD, ln2_b + l*DD);
        gemm_hmma<false><<<dim3(FF/128, gM, 1), 256, GSMEM>>>(
            hh, nullptr, w1p + (size_t)l*FF*DD,
            nullptr, mh, nullptr, MROWS, FF, DD, DD, b1 + (size_t)l*FF, nullptr, EPI_GELU);
        gemm_hmma<false><<<dim3(DD/128, gM, 2), 256, GSMEM>>>(
            mh, nullptr, w2p + (size_t)l*DD*FF,
            x, nullptr, nullptr, MROWS, DD, FF, FF/2, b2 + (size_t)l*DD, nullptr, EPI_RES_ATOM);
    }

    ln_f32_kernel<<<BB, 256>>>(x, clsb, lnf_g, lnf_b, SS);
    cls_head_kernel<<<(BB*NLAB*32 + 255)/256, 256>>>(clsb, cls_w, cls_b, out);
}

// round 17
// speedup vs baseline: 1.4358x; 1.0489x over previous
#include <cuda_runtime.h>
#include <cuda_fp16.h>
#include <math.h>
#include <stdint.h>

#define BB   32
#define SS   197
#define NTOK 196
#define DD   768
#define NHH  12
#define HDD  64
#define FF   3072
#define LLAY 12
#define NLAB 1000
#define MROWS (BB*SS)
#define MPAT  (BB*NTOK)
#define BHN   (BB*NHH)

// ===== Scratch =====
__device__ __half g_ph[MPAT * DD], g_pl[MPAT * DD];
__device__ __half g_hh[MROWS * DD], g_hl[MROWS * DD];
__device__ __half g_oh[MROWS * DD];
__device__ __half g_mh[MROWS * FF];
__device__ __half g_qkvh[MROWS * 3 * DD], g_qkvl[MROWS * DD];
__device__ __half g_wqkv[LLAY*3*DD*DD];
__device__ __half g_wo[LLAY*DD*DD];
__device__ __half g_w1[LLAY*FF*DD];
__device__ __half g_w2[LLAY*DD*FF];
__device__ __half g_pw[DD * DD];
__device__ float g_x[MROWS * DD];
__device__ float g_cls[BB * DD];

// ===== helpers =====
__device__ __forceinline__ uint32_t s2u(const void* p) {
    uint32_t a;
    asm("{ .reg .u64 t; cvta.to.shared.u64 t, %1; cvt.u32.u64 %0, t; }" : "=r"(a) : "l"(p));
    return a;
}
__device__ __forceinline__ void split_f16(float v, __half& h, __half& l) {
    h = __float2half_rn(v);
    l = __float2half_rn(v - __half2float(h));
}
__device__ __forceinline__ uint32_t pack_f16(float v0, float v1) {
    return ((uint32_t)__half_as_ushort(__float2half_rn(v1)) << 16)
         | __half_as_ushort(__float2half_rn(v0));
}
__device__ __forceinline__ uint32_t split_pack(float v0, float v1, uint32_t& lo) {
    __half h0, l0, h1, l1;
    split_f16(v0, h0, l0); split_f16(v1, h1, l1);
    lo = ((uint32_t)__half_as_ushort(l1) << 16) | __half_as_ushort(l0);
    return ((uint32_t)__half_as_ushort(h1) << 16) | __half_as_ushort(h0);
}
__device__ __forceinline__ void cpa16(uint32_t s, const void* g) {
    asm volatile("cp.async.cg.shared.global [%0], [%1], 16;"
        :: "r"(s), "l"(g) : "memory");
}
#define CP_COMMIT() asm volatile("cp.async.commit_group;" ::: "memory")
#define CP_WAIT2()  asm volatile("cp.async.wait_group 2;" ::: "memory")
#define CP_WAIT1()  asm volatile("cp.async.wait_group 1;" ::: "memory")
#define CP_WAIT0()  asm volatile("cp.async.wait_group 0;" ::: "memory")

__device__ __forceinline__ void ldm4(uint32_t* f, uint32_t a) {
    asm volatile("ldmatrix.sync.aligned.m8n8.x4.shared.b16 {%0,%1,%2,%3}, [%4];"
        : "=r"(f[0]), "=r"(f[1]), "=r"(f[2]), "=r"(f[3]) : "r"(a));
}
__device__ __forceinline__ void ldm4t(uint32_t* f, uint32_t a) {
    asm volatile("ldmatrix.sync.aligned.m8n8.x4.trans.shared.b16 {%0,%1,%2,%3}, [%4];"
        : "=r"(f[0]), "=r"(f[1]), "=r"(f[2]), "=r"(f[3]) : "r"(a));
}
__device__ __forceinline__ void mma16(float* c, const uint32_t* a, uint32_t b0, uint32_t b1) {
    asm volatile("mma.sync.aligned.m16n8k16.row.col.f32.f16.f16.f32 "
        "{%0,%1,%2,%3},{%4,%5,%6,%7},{%8,%9},{%0,%1,%2,%3};"
        : "+f"(c[0]), "+f"(c[1]), "+f"(c[2]), "+f"(c[3])
        : "r"(a[0]), "r"(a[1]), "r"(a[2]), "r"(a[3]), "r"(b0), "r"(b1));
}
__device__ __forceinline__ uint32_t swz(int row, int ch) {
    return (uint32_t)(row * 64) + (uint32_t)((ch ^ ((row >> 1) & 3)) << 4);
}
__device__ __forceinline__ uint32_t swz8(int row, int ch) {
    return (uint32_t)(row * 128) + (uint32_t)((ch ^ (row & 7)) << 4);
}

// ===== Weight transpose+convert: W[z][K][N] fp32 -> o[z][N][K] fp16 =====
__global__ void wconv_t_kernel(const float* __restrict__ W,
    __half* __restrict__ o, int K, int N)
{
    __shared__ float t[32][33];
    size_t ls = (size_t)blockIdx.z * K * N;
    const float* w = W + ls;
    int k0 = blockIdx.y * 32, n0 = blockIdx.x * 32;
    int tx = threadIdx.x, ty = threadIdx.y;
    for (int i = ty; i < 32; i += 8)
        t[i][tx] = w[(size_t)(k0 + i) * N + n0 + tx];
    __syncthreads();
    int tid = ty * 32 + tx;
    int c = tid & 7, i = tid >> 3;
    uint2 u;
    u.x = pack_f16(t[4*c + 0][i], t[4*c + 1][i]);
    u.y = pack_f16(t[4*c + 2][i], t[4*c + 3][i]);
    *(uint2*)(o + ls + (size_t)(n0 + i) * K + k0 + 4*c) = u;
}

__global__ __launch_bounds__(256) void wconv_kernel(const float* __restrict__ W,
    __half* __restrict__ o, int n4)
{
    int t = blockIdx.x * 256 + threadIdx.x;
    if (t >= n4) return;
    float4 v = *(const float4*)(W + (size_t)t * 4);
    uint2 u;
    u.x = pack_f16(v.x, v.y);
    u.y = pack_f16(v.z, v.w);
    *(uint2*)(o + (size_t)t * 4) = u;
}

// ===== Fixation gather -> fp16 hi/lo =====
__global__ __launch_bounds__(256) void gather_kernel(
    const float* __restrict__ px, const int* __restrict__ fix,
    __half* __restrict__ ph, __half* __restrict__ pl)
{
    int t = blockIdx.x * 256 + threadIdx.x;
    if (t >= MPAT * DD) return;
    int d = t % DD, row = t / DD;
    int b = row / NTOK, n = row % NTOK;
    int fx = fix[(b * NTOK + n) * 2 + 0];
    int fy = fix[(b * NTOK + n) * 2 + 1];
    int c = d >> 8, rem = d & 255, i = rem >> 4, j = rem & 15;
    bool valid = (fx >= 0) && (fy >= 0);
    int top  = min(max(fy - 8, 0), 208);
    int left = min(max(fx - 8, 0), 208);
    float v = 0.f;
    if (valid) v = px[(((size_t)b * 3 + c) * 224 + (top + i)) * 224 + (left + j)];
    __half h, l; split_f16(v, h, l);
    ph[t] = h; pl[t] = l;
}

__global__ __launch_bounds__(256) void cls_init_kernel(
    const float* __restrict__ ct, const float* __restrict__ pos, float* __restrict__ x)
{
    int t = blockIdx.x * 256 + threadIdx.x;
    if (t >= BB * DD) return;
    x[(size_t)(t / DD) * SS * DD + (t % DD)] = ct[t % DD] + pos[t % DD];
}

// ===== HMMA fp16 GEMM, TN=128, split-K via blockIdx.z, templated SPLITA =====
// CTA 128x128, BK=32, 256 threads (4x2 warps, warp tile 32x64), 4-stage, 2 CTA/SM.
#define OAL 8192
#define OBS 16384
#define STG 24576
#define GSMEM (4*STG)

#define EPI_BIAS     0
#define EPI_RES      1
#define EPI_GELU     2
#define EPI_PATCH    3
#define EPI_QKV      4
#define EPI_RES_ATOM 5

template<bool SPLITA>
__device__ __forceinline__ void load_stage(uint32_t sbase,
    const __half* Ah, const __half* Al, const __half* B,
    int m0, int n0, int K, int k0, int Mv, int tid)
{
    #pragma unroll
    for (int g = 0; g < 2; g++) {       // A: 128 rows x 4 chunks
        int idx = tid + g * 256;
        int row = idx >> 2, ch = idx & 3;
        uint32_t so = swz(row, ch);
        int ra = m0 + row;
        int rc = ra < Mv ? ra : (Mv - 1);
        size_t ga = (size_t)rc * K + k0 + ch * 8;
        cpa16(sbase + so, Ah + ga);
        if (SPLITA) cpa16(sbase + OAL + so, Al + ga);
    }
    #pragma unroll
    for (int g = 0; g < 2; g++) {       // B: 128 rows x 4 chunks (single)
        int idx = tid + g * 256;
        int row = idx >> 2, ch = idx & 3;
        uint32_t so = swz(row, ch);
        size_t gb = (size_t)(n0 + row) * K + k0 + ch * 8;
        cpa16(sbase + OBS + so, B + gb);
    }
}

template<bool SPLITA>
__global__ __launch_bounds__(256, 2) void gemm_hmma(
    const __half* __restrict__ Ah, const __half* __restrict__ Al,
    const __half* __restrict__ B,
    float* __restrict__ Cf, __half* __restrict__ Coh, __half* __restrict__ Col,
    int Mv, int N, int K, int Ksub,
    const float* __restrict__ bias, const float* __restrict__ pos, int mode)
{
    extern __shared__ char smem[];
    uint32_t sb = s2u(smem);
    int tid = threadIdx.x, wid = tid >> 5, lane = tid & 31;
    const int m0 = blockIdx.y * 128;
    const int n0 = blockIdx.x * 128;
    const int kBase = blockIdx.z * Ksub;
    const int wm = wid & 3, wn = wid >> 2;

    float acc[2][8][4];
    #pragma unroll
    for (int a = 0; a < 2; a++)
        #pragma unroll
        for (int b = 0; b < 8; b++)
            #pragma unroll
            for (int d = 0; d < 4; d++) acc[a][b][d] = 0.f;

    const int nk = Ksub / 32;
    #pragma unroll
    for (int s = 0; s < 3; s++) {
        load_stage<SPLITA>(sb + s * STG, Ah, Al, B, m0, n0, K, kBase + s * 32, Mv, tid);
        CP_COMMIT();
    }

    const int arow_l = (lane & 15);
    const int acsel  = (lane >> 4);
    const int brow_l = (lane & 7) + ((lane >> 4) << 3);
    const int bcsel  = ((lane >> 3) & 1);

    for (int kt = 0; kt < nk; kt++) {
        CP_WAIT2();
        __syncthreads();
        if (kt + 3 < nk)
            load_stage<SPLITA>(sb + ((kt + 3) & 3) * STG, Ah, Al, B, m0, n0, K, kBase + (kt + 3) * 32, Mv, tid);
        CP_COMMIT();

        uint32_t cs = sb + (kt & 3) * STG;
        #pragma unroll
        for (int ks = 0; ks < 2; ks++) {
            int cbase = ks * 2;
            uint32_t ah[2][4], al[2][4];
            #pragma unroll
            for (int mg = 0; mg < 2; mg++) {
                int r = wm * 32 + mg * 16 + arow_l;
                uint32_t a_ad = cs + swz(r, cbase + acsel);
                ldm4(ah[mg], a_ad);
                if (SPLITA) ldm4(al[mg], a_ad + OAL);
            }
            #pragma unroll
            for (int p = 0; p < 4; p++) {
                int br = wn * 64 + p * 16 + brow_l;
                uint32_t b_ad = cs + OBS + swz(br, cbase + bcsel);
                uint32_t bq[4];
                ldm4(bq, b_ad);
                #pragma unroll
                for (int mg = 0; mg < 2; mg++) {
                    #pragma unroll
                    for (int sub = 0; sub < 2; sub++) {
                        float* C = acc[mg][p * 2 + sub];
                        mma16(C, ah[mg], bq[sub * 2], bq[sub * 2 + 1]);
                        if (SPLITA) mma16(C, al[mg], bq[sub * 2], bq[sub * 2 + 1]);
                    }
                }
            }
        }
    }

    // Epilogue
    #pragma unroll
    for (int mg = 0; mg < 2; mg++) {
        #pragma unroll
        for (int ng = 0; ng < 8; ng++) {
            int col = n0 + wn * 64 + ng * 8 + 2 * (lane & 3);
            float2 bz = *(const float2*)(bias + col);
            #pragma unroll
            for (int half = 0; half < 2; half++) {
                int row = m0 + wm * 32 + mg * 16 + (lane >> 2) + half * 8;
                if (row >= Mv) continue;
                float a0 = acc[mg][ng][half * 2 + 0];
                float a1 = acc[mg][ng][half * 2 + 1];
                if (mode == EPI_RES_ATOM) {
                    if (blockIdx.z == 0) { a0 += bz.x; a1 += bz.y; }
                    atomicAdd(Cf + (size_t)row * N + col,     a0);
                    atomicAdd(Cf + (size_t)row * N + col + 1, a1);
                    continue;
                }
                float v0 = a0 + bz.x;
                float v1 = a1 + bz.y;
                if (mode == EPI_BIAS) {
                    *(float2*)(Cf + (size_t)row * N + col) = make_float2(v0, v1);
                } else if (mode == EPI_RES) {
                    float2 o = *(const float2*)(Cf + (size_t)row * N + col);
                    o.x += v0; o.y += v1;
                    *(float2*)(Cf + (size_t)row * N + col) = o;
                } else if (mode == EPI_GELU) {
                    v0 = 0.5f * v0 * (1.f + erff(v0 * 0.70710678118654752f));
                    v1 = 0.5f * v1 * (1.f + erff(v1 * 0.70710678118654752f));
                    *(uint32_t*)(Coh + (size_t)row * N + col) = pack_f16(v0, v1);
                } else if (mode == EPI_QKV) {
                    if (col < DD) {
                        // Q third: scale + hi/lo split
                        v0 *= 0.125f; v1 *= 0.125f;
                        uint32_t ul;
                        uint32_t uh = split_pack(v0, v1, ul);
                        *(uint32_t*)(Coh + (size_t)row * N + col) = uh;
                        *(uint32_t*)(Col + (size_t)row * DD + col) = ul;
                    } else {
                        // K/V thirds: hi only (lo never read)
                        *(uint32_t*)(Coh + (size_t)row * N + col) = pack_f16(v0, v1);
                    }
                } else { // EPI_PATCH
                    int b = row / NTOK, n = row % NTOK;
                    float2 pz = *(const float2*)(pos + (size_t)(n + 1) * DD + col);
                    v0 += pz.x; v1 += pz.y;
                    *(float2*)(Cf + (size_t)(b * SS + n + 1) * DD + col) = make_float2(v0, v1);
                }
            }
        }
    }
}

// ===== Flash attention (Q split 2-term vs K; P split vs V; O single fp16) =====
#define FQH 0
#define FQL 16384
#define FK  32768
#define FV  59392
#define FSMEM 86016

__global__ __launch_bounds__(256) void flash_kernel(
    const __half* __restrict__ QKVh, const __half* __restrict__ QKVl,
    __half* __restrict__ Oh)
{
    extern __shared__ char smem[];
    uint32_t sb = s2u(smem);
    int tid = threadIdx.x, wid = tid >> 5, lane = tid & 31;
    int bh = blockIdx.y, b = bh / NHH, h = bh % NHH;
    int qt = blockIdx.x * 128;
    const int R3D = 3 * DD;
    const int hoff = h * HDD;

    #pragma unroll
    for (int i = 0; i < 4; i++) {
        int idx = tid + i * 256;
        int row = idx >> 3, ch = idx & 7;
        int r = qt + row; if (r > SS - 1) r = SS - 1;
        size_t gq = (size_t)(b * SS + r) * R3D + hoff + ch * 8;
        size_t gl = (size_t)(b * SS + r) * DD + hoff + ch * 8;
        uint32_t so = swz8(row, ch);
        cpa16(sb + FQH + so, QKVh + gq);
        cpa16(sb + FQL + so, QKVl + gl);
    }
    #pragma unroll
    for (int i = 0; i < 7; i++) {
        int idx = tid + i * 256;
        if (idx < 1664) {
            int row = idx >> 3, ch = idx & 7;
            int r = row > SS - 1 ? SS - 1 : row;
            size_t g = (size_t)(b * SS + r) * R3D + DD + hoff + ch * 8;
            cpa16(sb + FK + swz8(row, ch), QKVh + g);
        }
    }
    CP_COMMIT();
    #pragma unroll
    for (int i = 0; i < 7; i++) {
        int idx = tid + i * 256;
        if (idx < 1664) {
            int row = idx >> 3, ch = idx & 7;
            int r = row > SS - 1 ? SS - 1 : row;
            size_t g = (size_t)(b * SS + r) * R3D + 2 * DD + hoff + ch * 8;
            cpa16(sb + FV + swz8(row, ch), QKVh + g);
        }
    }
    CP_COMMIT();
    CP_WAIT1();
    __syncthreads();

    float S[26][4];
    #pragma unroll
    for (int t = 0; t < 26; t++)
        #pragma unroll
        for (int e = 0; e < 4; e++) S[t][e] = 0.f;

    const int arow = lane & 15, acsel = lane >> 4;
    const int brow = (lane & 7) + ((lane >> 4) << 3), bcsel = (lane >> 3) & 1;

    #pragma unroll
    for (int ks = 0; ks < 4; ks++) {
        uint32_t qh[4], ql[4];
        uint32_t qa = sb + FQH + swz8(wid * 16 + arow, ks * 2 + acsel);
        ldm4(qh, qa);
        ldm4(ql, qa + (FQL - FQH));
        #pragma unroll
        for (int p = 0; p < 13; p++) {
            uint32_t kq[4];
            ldm4(kq, sb + FK + swz8(p * 16 + brow, ks * 2 + bcsel));
            #pragma unroll
            for (int sub = 0; sub < 2; sub++) {
                float* C = S[p * 2 + sub];
                mma16(C, qh, kq[sub * 2], kq[sub * 2 + 1]);
                mma16(C, ql, kq[sub * 2], kq[sub * 2 + 1]);
            }
        }
    }

    #pragma unroll
    for (int t = 24; t < 26; t++) {
        #pragma unroll
        for (int e = 0; e < 2; e++) {
            int colv = 8 * t + 2 * (lane & 3) + e;
            if (colv >= SS) { S[t][e] = -1e30f; S[t][2 + e] = -1e30f; }
        }
    }

    float m0 = -1e30f, m1 = -1e30f;
    #pragma unroll
    for (int t = 0; t < 26; t++) {
        m0 = fmaxf(m0, fmaxf(S[t][0], S[t][1]));
        m1 = fmaxf(m1, fmaxf(S[t][2], S[t][3]));
    }
    m0 = fmaxf(m0, __shfl_xor_sync(0xffffffff, m0, 1));
    m0 = fmaxf(m0, __shfl_xor_sync(0xffffffff, m0, 2));
    m1 = fmaxf(m1, __shfl_xor_sync(0xffffffff, m1, 1));
    m1 = fmaxf(m1, __shfl_xor_sync(0xffffffff, m1, 2));
    float s0 = 0.f, s1 = 0.f;
    #pragma unroll
    for (int t = 0; t < 26; t++) {
        S[t][0] = __expf(S[t][0] - m0); S[t][1] = __expf(S[t][1] - m0);
        S[t][2] = __expf(S[t][2] - m1); S[t][3] = __expf(S[t][3] - m1);
        s0 += S[t][0] + S[t][1];
        s1 += S[t][2] + S[t][3];
    }
    s0 += __shfl_xor_sync(0xffffffff, s0, 1);
    s0 += __shfl_xor_sync(0xffffffff, s0, 2);
    s1 += __shfl_xor_sync(0xffffffff, s1, 1);
    s1 += __shfl_xor_sync(0xffffffff, s1, 2);
    float inv0 = 1.f / s0, inv1 = 1.f / s1;

    CP_WAIT0();
    __syncthreads();

    float Cv[8][4];
    #pragma unroll
    for (int d = 0; d < 8; d++)
        #pragma unroll
        for (int e = 0; e < 4; e++) Cv[d][e] = 0.f;

    const int jr = (lane & 7) + (((lane >> 3) & 1) << 3);
    const int csel = lane >> 4;

    #pragma unroll
    for (int t = 0; t < 13; t++) {
        uint32_t aph[4], apl[4];
        aph[0] = split_pack(S[2*t][0],   S[2*t][1],   apl[0]);
        aph[1] = split_pack(S[2*t][2],   S[2*t][3],   apl[1]);
        aph[2] = split_pack(S[2*t+1][0], S[2*t+1][1], apl[2]);
        aph[3] = split_pack(S[2*t+1][2], S[2*t+1][3], apl[3]);
        #pragma unroll
        for (int dt = 0; dt < 4; dt++) {
            uint32_t vq[4];
            ldm4t(vq, sb + FV + swz8(t * 16 + jr, dt * 2 + csel));
            #pragma unroll
            for (int sub = 0; sub < 2; sub++) {
                float* C = Cv[dt * 2 + sub];
                mma16(C, aph, vq[sub * 2], vq[sub * 2 + 1]);
                mma16(C, apl, vq[sub * 2], vq[sub * 2 + 1]);
            }
        }
    }

    int r0 = qt + wid * 16 + (lane >> 2);
    int r1 = r0 + 8;
    #pragma unroll
    for (int nt = 0; nt < 8; nt++) {
        int col = hoff + nt * 8 + 2 * (lane & 3);
        if (r0 < SS)
            *(uint32_t*)(Oh + (size_t)(b * SS + r0) * DD + col) =
                pack_f16(Cv[nt][0] * inv0, Cv[nt][1] * inv0);
        if (r1 < SS)
            *(uint32_t*)(Oh + (size_t)(b * SS + r1) * DD + col) =
                pack_f16(Cv[nt][2] * inv1, Cv[nt][3] * inv1);
    }
}

// ===== LayerNorm: warp per row; SPLIT=true -> hi/lo, false -> single fp16 =====
template<bool SPLIT>
__global__ __launch_bounds__(256) void ln_f16_kernel(
    const float* __restrict__ x, __half* __restrict__ oh, __half* __restrict__ ol,
    const float* __restrict__ g, const float* __restrict__ bb)
{
    int wid = threadIdx.x >> 5, lane = threadIdx.x & 31;
    int row = blockIdx.x * 8 + wid;
    const float* xr = x + (size_t)row * DD;
    float4 v[6];
    float sum = 0.f;
    #pragma unroll
    for (int j = 0; j < 6; j++) {
        v[j] = *(const float4*)(xr + j * 128 + lane * 4);
        sum += v[j].x + v[j].y + v[j].z + v[j].w;
    }
    #pragma unroll
    for (int o = 16; o > 0; o >>= 1) sum += __shfl_xor_sync(0xffffffff, sum, o);
    float mu = sum * (1.f / 768.f);
    float var = 0.f;
    #pragma unroll
    for (int j = 0; j < 6; j++) {
        v[j].x -= mu; v[j].y -= mu; v[j].z -= mu; v[j].w -= mu;
        var += v[j].x * v[j].x + v[j].y * v[j].y + v[j].z * v[j].z + v[j].w * v[j].w;
    }
    #pragma unroll
    for (int o = 16; o > 0; o >>= 1) var += __shfl_xor_sync(0xffffffff, var, o);
    float rs = rsqrtf(var * (1.f / 768.f) + 1e-12f);
    size_t base = (size_t)row * DD;
    #pragma unroll
    for (int j = 0; j < 6; j++) {
        int col = j * 128 + lane * 4;
        float4 gg = *(const float4*)(g + col);
        float4 bz = *(const float4*)(bb + col);
        float y0 = v[j].x * rs * gg.x + bz.x;
        float y1 = v[j].y * rs * gg.y + bz.y;
        float y2 = v[j].z * rs * gg.z + bz.z;
        float y3 = v[j].w * rs * gg.w + bz.w;
        if (SPLIT) {
            uint2 uh, ul;
            uh.x = split_pack(y0, y1, ul.x);
            uh.y = split_pack(y2, y3, ul.y);
            *(uint2*)(oh + base + col) = uh;
            *(uint2*)(ol + base + col) = ul;
        } else {
            uint2 uh;
            uh.x = pack_f16(y0, y1);
            uh.y = pack_f16(y2, y3);
            *(uint2*)(oh + base + col) = uh;
        }
    }
}

__device__ __forceinline__ float block_reduce_sum(float v, float* red) {
    int tid = threadIdx.x;
    red[tid] = v; __syncthreads();
    #pragma unroll
    for (int s = 128; s > 0; s >>= 1) { if (tid < s) red[tid] += red[tid + s]; __syncthreads(); }
    float r = red[0]; __syncthreads();
    return r;
}

__global__ __launch_bounds__(256) void ln_f32_kernel(
    const float* __restrict__ x, float* __restrict__ o,
    const float* __restrict__ g, const float* __restrict__ bb, int rowstep)
{
    __shared__ float red[256];
    const float* xr = x + (size_t)blockIdx.x * rowstep * DD;
    float* orow = o + (size_t)blockIdx.x * DD;
    int tid = threadIdx.x;
    float v0 = xr[tid], v1 = xr[tid + 256], v2 = xr[tid + 512];
    float mu = block_reduce_sum(v0 + v1 + v2, red) * (1.f / 768.f);
    float d0 = v0 - mu, d1 = v1 - mu, d2 = v2 - mu;
    float var = block_reduce_sum(d0*d0 + d1*d1 + d2*d2, red) * (1.f / 768.f);
    float rs = rsqrtf(var + 1e-12f);
    orow[tid]     = d0*rs*g[tid]     + bb[tid];
    orow[tid+256] = d1*rs*g[tid+256] + bb[tid+256];
    orow[tid+512] = d2*rs*g[tid+512] + bb[tid+512];
}

__global__ __launch_bounds__(256) void cls_head_kernel(
    const float* __restrict__ xc, const float* __restrict__ w,
    const float* __restrict__ bias, float* __restrict__ out)
{
    int wid = (blockIdx.x * 256 + threadIdx.x) >> 5;
    int lane = threadIdx.x & 31;
    if (wid >= BB * NLAB) return;
    int b = wid / NLAB, n = wid % NLAB;
    const float* xr = xc + (size_t)b * DD;
    const float* wr = w + (size_t)n * DD;
    float s = 0.f;
    for (int k = lane * 4; k < DD; k += 128) {
        float4 a = *(const float4*)(xr + k);
        float4 c = *(const float4*)(wr + k);
        s += a.x*c.x + a.y*c.y + a.z*c.z + a.w*c.w;
    }
    #pragma unroll
    for (int o = 16; o > 0; o >>= 1) s += __shfl_xor_sync(0xffffffff, s, o);
    if (lane == 0) out[(size_t)b * NLAB + n] = s + bias[n];
}

// ===== Host =====
extern "C" void kernel_launch(void* const* d_in, const int* in_sizes, int n_in,
                              void* d_out, int out_size) {
    const float* px      = (const float*)d_in[0];
    const int*   fix     = (const int*)  d_in[1];
    const float* patch_w = (const float*)d_in[2];
    const float* patch_b = (const float*)d_in[3];
    const float* cls_tok = (const float*)d_in[4];
    const float* pos_emb = (const float*)d_in[5];
    const float* ln1_g   = (const float*)d_in[6];
    const float* ln1_b   = (const float*)d_in[7];
    const float* wqkv    = (const float*)d_in[8];
    const float* bqkv    = (const float*)d_in[9];
    const float* wo      = (const float*)d_in[10];
    const float* bo      = (const float*)d_in[11];
    const float* ln2_g   = (const float*)d_in[12];
    const float* ln2_b   = (const float*)d_in[13];
    const float* w1      = (const float*)d_in[14];
    const float* b1      = (const float*)d_in[15];
    const float* w2      = (const float*)d_in[16];
    const float* b2      = (const float*)d_in[17];
    const float* lnf_g   = (const float*)d_in[18];
    const float* lnf_b   = (const float*)d_in[19];
    const float* cls_w   = (const float*)d_in[20];
    const float* cls_b   = (const float*)d_in[21];
    float* out = (float*)d_out;

    __half *ph,*pl,*hh,*hl,*oh,*mh,*qkvh,*qkvl;
    __half *wq,*wop,*w1p,*w2p,*pwp;
    float *x,*clsb;
    cudaGetSymbolAddress((void**)&ph, g_ph);   cudaGetSymbolAddress((void**)&pl, g_pl);
    cudaGetSymbolAddress((void**)&hh, g_hh);   cudaGetSymbolAddress((void**)&hl, g_hl);
    cudaGetSymbolAddress((void**)&oh, g_oh);
    cudaGetSymbolAddress((void**)&mh, g_mh);
    cudaGetSymbolAddress((void**)&qkvh, g_qkvh); cudaGetSymbolAddress((void**)&qkvl, g_qkvl);
    cudaGetSymbolAddress((void**)&wq, g_wqkv);
    cudaGetSymbolAddress((void**)&wop, g_wo);
    cudaGetSymbolAddress((void**)&w1p, g_w1);
    cudaGetSymbolAddress((void**)&w2p, g_w2);
    cudaGetSymbolAddress((void**)&pwp, g_pw);
    cudaGetSymbolAddress((void**)&x, g_x);     cudaGetSymbolAddress((void**)&clsb, g_cls);

    cudaFuncSetAttribute((const void*)gemm_hmma<true>,  cudaFuncAttributeMaxDynamicSharedMemorySize, GSMEM);
    cudaFuncSetAttribute((const void*)gemm_hmma<false>, cudaFuncAttributeMaxDynamicSharedMemorySize, GSMEM);
    cudaFuncSetAttribute(flash_kernel, cudaFuncAttributeMaxDynamicSharedMemorySize, FSMEM);

    static cudaStream_t s2 = nullptr;
    static cudaEvent_t evF = nullptr, evJ = nullptr;
    if (s2 == nullptr) {
        cudaStreamCreateWithFlags(&s2, cudaStreamNonBlocking);
        cudaEventCreateWithFlags(&evF, cudaEventDisableTiming);
        cudaEventCreateWithFlags(&evJ, cudaEventDisableTiming);
    }

    // Fork: weight conversions on s2 overlap gather/patch-embed
    cudaEventRecord(evF, 0);
    cudaStreamWaitEvent(s2, evF, 0);
    wconv_t_kernel<<<dim3(3*DD/32, DD/32, LLAY), dim3(32,8), 0, s2>>>(wqkv, wq, DD, 3*DD);
    wconv_t_kernel<<<dim3(DD/32,   DD/32, LLAY), dim3(32,8), 0, s2>>>(wo,   wop, DD, DD);
    wconv_t_kernel<<<dim3(FF/32,   DD/32, LLAY), dim3(32,8), 0, s2>>>(w1,   w1p, DD, FF);
    wconv_t_kernel<<<dim3(DD/32,   FF/32, LLAY), dim3(32,8), 0, s2>>>(w2,   w2p, FF, DD);
    cudaEventRecord(evJ, s2);

    gather_kernel<<<(MPAT*DD + 255)/256, 256>>>(px, fix, ph, pl);
    wconv_kernel<<<(DD*DD/4 + 255)/256, 256>>>(patch_w, pwp, DD*DD/4);
    cls_init_kernel<<<(BB*DD + 255)/256, 256>>>(cls_tok, pos_emb, x);
    gemm_hmma<true><<<dim3(DD/128, (MPAT + 127)/128, 1), 256, GSMEM>>>(
        ph, pl, pwp, x, nullptr, nullptr, MPAT, DD, DD, DD, patch_b, pos_emb, EPI_PATCH);

    cudaStreamWaitEvent(0, evJ, 0);

    const int gM = (MROWS + 127) / 128;  // 50
    for (int l = 0; l < LLAY; l++) {
        ln_f16_kernel<true><<<MROWS/8, 256>>>(x, hh, hl, ln1_g + l*DD, ln1_b + l*DD);
        gemm_hmma<true><<<dim3(3*DD/128, gM, 1), 256, GSMEM>>>(
            hh, hl, wq + (size_t)l*3*DD*DD,
            nullptr, qkvh, qkvl, MROWS, 3*DD, DD, DD, bqkv + (size_t)l*3*DD, nullptr, EPI_QKV);
        flash_kernel<<<dim3(2, BHN), 256, FSMEM>>>(qkvh, qkvl, oh);
        gemm_hmma<false><<<dim3(DD/128, gM, 2), 256, GSMEM>>>(
            oh, nullptr, wop + (size_t)l*DD*DD,
            x, nullptr, nullptr, MROWS, DD, DD, DD/2, bo + (size_t)l*DD, nullptr, EPI_RES_ATOM);
        ln_f16_kernel<false><<<MROWS/8, 256>>>(x, hh, nullptr, ln2_g + l*DD, ln2_b + l*DD);
        gemm_hmma<false><<<dim3(FF/128, gM, 1), 256, GSMEM>>>(
            hh, nullptr, w1p + (size_t)l*FF*DD,
            nullptr, mh, nullptr, MROWS, FF, DD, DD, b1 + (size_t)l*FF, nullptr, EPI_GELU);
        gemm_hmma<false><<<dim3(DD/128, gM, 2), 256, GSMEM>>>(
            mh, nullptr, w2p + (size_t)l*DD*FF,
            x, nullptr, nullptr, MROWS, DD, FF, FF/2, b2 + (size_t)l*DD, nullptr, EPI_RES_ATOM);
    }

    ln_f32_kernel<<<BB, 256>>>(x, clsb, lnf_g, lnf_b, SS);
    cls_head_kernel<<<(BB*NLAB*32 + 255)/256, 256>>>(clsb, cls_w, cls_b, out);
}